// round 1
// baseline (speedup 1.0000x reference)
#include <cuda_runtime.h>
#include <cuda_bf16.h>
#include <math.h>

// Problem dims (fixed by the dataset)
#define BB 16
#define TT 4096
#define HH 256
#define PP 64

// ---------------- scratch (no allocation allowed) ----------------
__device__ float g_k1[BB * TT * HH];   // 64 MB
__device__ float g_v1[BB * TT * HH];   // 64 MB
__device__ float g_q2[BB * TT * HH];   // 64 MB
__device__ float g_q1[PP * HH];
__device__ float g_pf[BB * PP * HH];
__device__ float g_k2[BB * PP * HH];
__device__ float g_v2[BB * PP * HH];
__device__ float g_s1[BB * PP * TT];   // 16 MB
__device__ float g_s2[BB * TT * PP];   // 16 MB

// ---------------- tiled GEMM, C[m,n] = sum_k A[m,k] * B[n,k]  (TN) -------
// A: [M,K] row-major, B: [N,K] row-major (i.e. x @ W^T pattern).
// Optional bias[n], scale, and per-batch length masking (col n >= len -> -1e9,
// scale = rsqrt(len)).  Batched via blockIdx.z with element strides.
#define BM 64
#define BN 64
#define BKK 16
#define TM 4
#define TN 4

__global__ __launch_bounds__(256) void gemm_tn(
    const float* __restrict__ A, long long sA,
    const float* __restrict__ B, long long sB,
    float* __restrict__ C, long long sC,
    int M, int N, int K,
    const float* __restrict__ bias,
    float scale,
    const float* __restrict__ lens)
{
    __shared__ float As[BKK][BM + 1];
    __shared__ float Bs[BKK][BN + 1];

    const int bz = blockIdx.z;
    const float* Ab = A + (long long)bz * sA;
    const float* Bb = B + (long long)bz * sB;
    float* Cb = C + (long long)bz * sC;

    const int m0 = blockIdx.y * BM;
    const int n0 = blockIdx.x * BN;

    float maskLen = 3.0e38f;
    if (lens) {
        float L = lens[bz];
        scale = rsqrtf(L);
        maskLen = L;
    }

    const int tid = threadIdx.x;
    const int tx = tid % 16;       // n subgroup
    const int ty = tid / 16;       // m subgroup
    const int lk = tid % BKK;      // 0..15 : k within tile
    const int lr = tid / BKK;      // 0..15 : row start (step 16)

    float acc[TM][TN];
#pragma unroll
    for (int i = 0; i < TM; i++)
#pragma unroll
        for (int j = 0; j < TN; j++) acc[i][j] = 0.f;

    for (int k0 = 0; k0 < K; k0 += BKK) {
#pragma unroll
        for (int r = 0; r < BM; r += 16)
            As[lk][lr + r] = Ab[(long long)(m0 + lr + r) * K + k0 + lk];
#pragma unroll
        for (int r = 0; r < BN; r += 16)
            Bs[lk][lr + r] = Bb[(long long)(n0 + lr + r) * K + k0 + lk];
        __syncthreads();

#pragma unroll
        for (int kk = 0; kk < BKK; kk++) {
            float a[TM], b[TN];
#pragma unroll
            for (int i = 0; i < TM; i++) a[i] = As[kk][ty * TM + i];
#pragma unroll
            for (int j = 0; j < TN; j++) b[j] = Bs[kk][tx * TN + j];
#pragma unroll
            for (int i = 0; i < TM; i++)
#pragma unroll
                for (int j = 0; j < TN; j++) acc[i][j] += a[i] * b[j];
        }
        __syncthreads();
    }

#pragma unroll
    for (int i = 0; i < TM; i++) {
        const int m = m0 + ty * TM + i;
#pragma unroll
        for (int j = 0; j < TN; j++) {
            const int n = n0 + tx * TN + j;
            float v = acc[i][j] * scale;
            if (bias) v += bias[n];
            if (lens && (float)n >= maskLen) v = -1e9f;
            Cb[(long long)m * N + n] = v;
        }
    }
}

// ---------------- tiled GEMM, C[m,n] = sum_k A[m,k] * B[k,n]  (NN) -------
__global__ __launch_bounds__(256) void gemm_nn(
    const float* __restrict__ A, long long sA,
    const float* __restrict__ B, long long sB,
    float* __restrict__ C, long long sC,
    int M, int N, int K)
{
    __shared__ float As[BKK][BM + 1];
    __shared__ float Bs[BKK][BN + 1];

    const int bz = blockIdx.z;
    const float* Ab = A + (long long)bz * sA;
    const float* Bb = B + (long long)bz * sB;
    float* Cb = C + (long long)bz * sC;

    const int m0 = blockIdx.y * BM;
    const int n0 = blockIdx.x * BN;

    const int tid = threadIdx.x;
    const int tx = tid % 16;
    const int ty = tid / 16;
    const int lk = tid % BKK;      // for A load
    const int lr = tid / BKK;
    const int ln = tid % BN;       // for B load
    const int lkk = tid / BN;      // 0..3

    float acc[TM][TN];
#pragma unroll
    for (int i = 0; i < TM; i++)
#pragma unroll
        for (int j = 0; j < TN; j++) acc[i][j] = 0.f;

    for (int k0 = 0; k0 < K; k0 += BKK) {
#pragma unroll
        for (int r = 0; r < BM; r += 16)
            As[lk][lr + r] = Ab[(long long)(m0 + lr + r) * K + k0 + lk];
#pragma unroll
        for (int kk2 = 0; kk2 < BKK; kk2 += 4)
            Bs[lkk + kk2][ln] = Bb[(long long)(k0 + lkk + kk2) * N + n0 + ln];
        __syncthreads();

#pragma unroll
        for (int kk = 0; kk < BKK; kk++) {
            float a[TM], b[TN];
#pragma unroll
            for (int i = 0; i < TM; i++) a[i] = As[kk][ty * TM + i];
#pragma unroll
            for (int j = 0; j < TN; j++) b[j] = Bs[kk][tx * TN + j];
#pragma unroll
            for (int i = 0; i < TM; i++)
#pragma unroll
                for (int j = 0; j < TN; j++) acc[i][j] += a[i] * b[j];
        }
        __syncthreads();
    }

#pragma unroll
    for (int i = 0; i < TM; i++) {
        const int m = m0 + ty * TM + i;
#pragma unroll
        for (int j = 0; j < TN; j++) {
            const int n = n0 + tx * TN + j;
            Cb[(long long)m * N + n] = acc[i][j];
        }
    }
}

// ---------------- softmax over rows (warp per row), in place -------------
__global__ void softmax_rows(float* __restrict__ x, int rows, int cols)
{
    const int row = blockIdx.x * (blockDim.x / 32) + (threadIdx.x / 32);
    if (row >= rows) return;
    const int lane = threadIdx.x & 31;
    float* p = x + (long long)row * cols;

    float m = -3.0e38f;
    for (int c = lane; c < cols; c += 32) m = fmaxf(m, p[c]);
#pragma unroll
    for (int o = 16; o; o >>= 1) m = fmaxf(m, __shfl_xor_sync(0xffffffffu, m, o));

    float s = 0.f;
    for (int c = lane; c < cols; c += 32) {
        float e = __expf(p[c] - m);
        p[c] = e;
        s += e;
    }
#pragma unroll
    for (int o = 16; o; o >>= 1) s += __shfl_xor_sync(0xffffffffu, s, o);

    const float inv = 1.f / s;
    for (int c = lane; c < cols; c += 32) p[c] *= inv;
}

// ---------------- launch -------------------------------------------------
extern "C" void kernel_launch(void* const* d_in, const int* in_sizes, int n_in,
                              void* d_out, int out_size)
{
    const float* hs    = (const float*)d_in[0];
    const float* proto = (const float*)d_in[1];
    const float* lens  = (const float*)d_in[2];
    // d_in[3] = mask (bool) — unused; reconstructed from lens
    const float* Q1w = (const float*)d_in[4];
    const float* Q1b = (const float*)d_in[5];
    const float* K1w = (const float*)d_in[6];
    const float* K1b = (const float*)d_in[7];
    const float* V1w = (const float*)d_in[8];
    const float* V1b = (const float*)d_in[9];
    const float* Qw  = (const float*)d_in[10];
    const float* Qb  = (const float*)d_in[11];
    const float* Kw  = (const float*)d_in[12];
    const float* Kb  = (const float*)d_in[13];
    const float* Vw  = (const float*)d_in[14];
    const float* Vb  = (const float*)d_in[15];
    float* out = (float*)d_out;

    float *k1, *v1, *q2, *q1, *pf, *k2, *v2, *s1, *s2;
    cudaGetSymbolAddress((void**)&k1, g_k1);
    cudaGetSymbolAddress((void**)&v1, g_v1);
    cudaGetSymbolAddress((void**)&q2, g_q2);
    cudaGetSymbolAddress((void**)&q1, g_q1);
    cudaGetSymbolAddress((void**)&pf, g_pf);
    cudaGetSymbolAddress((void**)&k2, g_k2);
    cudaGetSymbolAddress((void**)&v2, g_v2);
    cudaGetSymbolAddress((void**)&s1, g_s1);
    cudaGetSymbolAddress((void**)&s2, g_s2);

    const dim3 blk(256);
    const int BT = BB * TT;        // 65536
    const int BP = BB * PP;        // 1024

    // q1 = proto @ Q1_w^T + Q1_b                    [64, 256]
    gemm_tn<<<dim3(HH / BN, 1, 1), blk>>>(proto, 0, Q1w, 0, q1, 0,
                                          PP, HH, HH, Q1b, 1.f, nullptr);
    // k1 / v1 / q2 over all tokens                  [65536, 256]
    gemm_tn<<<dim3(HH / BN, BT / BM, 1), blk>>>(hs, 0, K1w, 0, k1, 0,
                                                BT, HH, HH, K1b, 1.f, nullptr);
    gemm_tn<<<dim3(HH / BN, BT / BM, 1), blk>>>(hs, 0, V1w, 0, v1, 0,
                                                BT, HH, HH, V1b, 1.f, nullptr);
    gemm_tn<<<dim3(HH / BN, BT / BM, 1), blk>>>(hs, 0, Qw, 0, q2, 0,
                                                BT, HH, HH, Qb, 1.f, nullptr);

    // scores1[b,p,t] = q1 . k1 * rsqrt(len_b), masked (t >= len -> -1e9)
    gemm_tn<<<dim3(TT / BN, PP / BM, BB), blk>>>(
        q1, 0, k1, (long long)TT * HH, s1, (long long)PP * TT,
        PP, TT, HH, nullptr, 1.f, lens);

    softmax_rows<<<(BP + 7) / 8, 256>>>(s1, BP, TT);

    // pf[b] = attn1 @ v1                            [64, 256] per batch
    gemm_nn<<<dim3(HH / BN, PP / BM, BB), blk>>>(
        s1, (long long)PP * TT, v1, (long long)TT * HH, pf, (long long)PP * HH,
        PP, HH, TT);

    // k2 / v2 = pf @ {K,V}_w^T + b                  [1024, 256]
    gemm_tn<<<dim3(HH / BN, BP / BM, 1), blk>>>(pf, 0, Kw, 0, k2, 0,
                                                BP, HH, HH, Kb, 1.f, nullptr);
    gemm_tn<<<dim3(HH / BN, BP / BM, 1), blk>>>(pf, 0, Vw, 0, v2, 0,
                                                BP, HH, HH, Vb, 1.f, nullptr);

    // scores2[b,t,p] = q2 . k2 / sqrt(P)
    gemm_tn<<<dim3(PP / BN, TT / BM, BB), blk>>>(
        q2, (long long)TT * HH, k2, (long long)PP * HH, s2, (long long)TT * PP,
        TT, PP, HH, nullptr, 0.125f, nullptr);

    softmax_rows<<<BT / 8, 256>>>(s2, BT, PP);

    // out[b] = attn2 @ v2                           [4096, 256] per batch
    gemm_nn<<<dim3(HH / BN, TT / BM, BB), blk>>>(
        s2, (long long)TT * PP, v2, (long long)PP * HH, out, (long long)TT * HH,
        TT, HH, PP);
}

// round 2
// speedup vs baseline: 1.8545x; 1.8545x over previous
#include <cuda_runtime.h>
#include <cuda_bf16.h>
#include <math.h>

// Problem dims (fixed by the dataset)
#define BB 16
#define TT 4096
#define HH 256
#define PP 64

#define NSPLIT 8   // split-K factor for the pf GEMM

// ---------------- scratch (no allocation allowed) ----------------
__device__ float g_k1[BB * TT * HH];   // 64 MB
__device__ float g_v1[BB * TT * HH];   // 64 MB
__device__ float g_q2[BB * TT * HH];   // 64 MB
__device__ float g_q1[PP * HH];
__device__ float g_pf[BB * PP * HH];
__device__ float g_pfp[NSPLIT * BB * PP * HH];  // split-K partials (8 MB)
__device__ float g_k2[BB * PP * HH];
__device__ float g_v2[BB * PP * HH];
__device__ float g_s1[BB * PP * TT];   // 16 MB
__device__ float g_s2[BB * TT * PP];   // 16 MB

// ---------------- f32x2 helpers -----------------------------------------
__device__ __forceinline__ unsigned long long pk2(float lo, float hi) {
    unsigned long long r;
    asm("mov.b64 %0, {%1, %2};" : "=l"(r) : "f"(lo), "f"(hi));
    return r;
}
__device__ __forceinline__ void unpk2(unsigned long long v, float& lo, float& hi) {
    asm("mov.b64 {%0, %1}, %2;" : "=f"(lo), "=f"(hi) : "l"(v));
}
__device__ __forceinline__ void fma2(unsigned long long& d,
                                     unsigned long long a,
                                     unsigned long long b) {
    asm("fma.rn.f32x2 %0, %1, %2, %0;" : "+l"(d) : "l"(a), "l"(b));
}

// ---------------- templated GEMM with packed f32x2 FMA -------------------
// C[m,n] = sum_k A[m,k] * B'[k,n]
//   BTRANS=true :  B' = B^T with B [N,K] row-major (x @ W^T pattern)
//   BTRANS=false:  B' = B     with B [K,N] row-major
// 256 threads, 16x16 layout, microtile (BM/16)x(BN/16); BN/16 must be even.
// Optional: bias[n], scale, per-batch length mask (col n >= len -> -1e9 and
// scale := rsqrt(len)), and split-K (nsplit chunks of Kloop, partials strided
// by sSplit in C).
#define BK 16
#define SPAD 4

template<int BM, int BN, bool BTRANS>
__global__ __launch_bounds__(256, 2) void gemm_f2(
    const float* __restrict__ A, long long sA, int lda,
    const float* __restrict__ B, long long sB, int ldb,
    float* __restrict__ C, long long sC, int ldc,
    int Kloop,
    const float* __restrict__ bias, float scale,
    const float* __restrict__ lens,
    int nsplit, long long sSplit)
{
    constexpr int MT = BM / 16;
    constexpr int NT = BN / 16;
    constexpr int NT2 = NT / 2;

    __shared__ float As[BK][BM + SPAD];
    __shared__ float Bs[BK][BN + SPAD];

    const int bz = blockIdx.z;
    const int b  = bz / nsplit;
    const int ks = bz % nsplit;

    const float* Ab = A + (long long)b * sA + (long long)ks * Kloop;
    const float* Bb;
    if (BTRANS) Bb = B + (long long)b * sB + (long long)ks * Kloop;
    else        Bb = B + (long long)b * sB + (long long)ks * Kloop * ldb;
    float* Cb = C + (long long)b * sC + (long long)ks * sSplit;

    const int m0 = blockIdx.y * BM;
    const int n0 = blockIdx.x * BN;

    float maskLen = 3.0e38f;
    if (lens) {
        float L = lens[b];
        scale = rsqrtf(L);
        maskLen = L;
    }

    const int tid = threadIdx.x;
    const int tx = tid % 16;
    const int ty = tid / 16;

    // loader indices
    const int lr  = tid >> 2;          // 0..63 (row for transposed loads)
    const int lkq = (tid & 3) * 4;     // k quad base

    unsigned long long acc[MT][NT2];
#pragma unroll
    for (int i = 0; i < MT; i++)
#pragma unroll
        for (int j = 0; j < NT2; j++) acc[i][j] = 0ULL;

    for (int k0 = 0; k0 < Kloop; k0 += BK) {
        // ---- load A tile: As[k][m] = A[m0+m][k0+k] ----
#pragma unroll
        for (int i = 0; i < BM / 64; i++) {
            const int m = lr + 64 * i;
            const float4 v = *(const float4*)(Ab + (long long)(m0 + m) * lda + k0 + lkq);
            As[lkq + 0][m] = v.x;
            As[lkq + 1][m] = v.y;
            As[lkq + 2][m] = v.z;
            As[lkq + 3][m] = v.w;
        }
        // ---- load B tile ----
        if (BTRANS) {
#pragma unroll
            for (int i = 0; i < BN / 64; i++) {
                const int n = lr + 64 * i;
                const float4 v = *(const float4*)(Bb + (long long)(n0 + n) * ldb + k0 + lkq);
                Bs[lkq + 0][n] = v.x;
                Bs[lkq + 1][n] = v.y;
                Bs[lkq + 2][n] = v.z;
                Bs[lkq + 3][n] = v.w;
            }
        } else {
            constexpr int PER_ROW = BN / 4;
            const int kk0 = tid / PER_ROW;
            const int nq  = (tid % PER_ROW) * 4;
#pragma unroll
            for (int i = 0; i < BN / 64; i++) {
                const int krow = kk0 + i * (256 / PER_ROW);
                const float4 v = *(const float4*)(Bb + (long long)(k0 + krow) * ldb + n0 + nq);
                *(float4*)&Bs[krow][nq] = v;
            }
        }
        __syncthreads();

        // ---- compute ----
#pragma unroll
        for (int kk = 0; kk < BK; kk++) {
            float a_reg[MT], b_reg[NT];
#pragma unroll
            for (int i4 = 0; i4 < MT; i4 += 4) {
                const float4 t = *(const float4*)(&As[kk][ty * MT + i4]);
                a_reg[i4 + 0] = t.x; a_reg[i4 + 1] = t.y;
                a_reg[i4 + 2] = t.z; a_reg[i4 + 3] = t.w;
            }
#pragma unroll
            for (int j4 = 0; j4 < NT; j4 += 4) {
                const float4 t = *(const float4*)(&Bs[kk][tx * NT + j4]);
                b_reg[j4 + 0] = t.x; b_reg[j4 + 1] = t.y;
                b_reg[j4 + 2] = t.z; b_reg[j4 + 3] = t.w;
            }
            unsigned long long bb[NT2];
#pragma unroll
            for (int j = 0; j < NT2; j++) bb[j] = pk2(b_reg[2 * j], b_reg[2 * j + 1]);
#pragma unroll
            for (int i = 0; i < MT; i++) {
                const unsigned long long aa = pk2(a_reg[i], a_reg[i]);
#pragma unroll
                for (int j = 0; j < NT2; j++) fma2(acc[i][j], aa, bb[j]);
            }
        }
        __syncthreads();
    }

    // ---- epilogue ----
    float bv[NT];
    bool msk[NT];
#pragma unroll
    for (int j = 0; j < NT; j++) {
        const int n = n0 + tx * NT + j;
        bv[j] = bias ? bias[n] : 0.f;
        msk[j] = lens ? ((float)n >= maskLen) : false;
    }

#pragma unroll
    for (int i = 0; i < MT; i++) {
        const int m = m0 + ty * MT + i;
        float* crow = Cb + (long long)m * ldc + n0 + tx * NT;
        float o[NT];
#pragma unroll
        for (int j = 0; j < NT2; j++) unpk2(acc[i][j], o[2 * j], o[2 * j + 1]);
#pragma unroll
        for (int j = 0; j < NT; j++) {
            float v = o[j] * scale + bv[j];
            if (msk[j]) v = -1e9f;
            o[j] = v;
        }
#pragma unroll
        for (int j4 = 0; j4 < NT; j4 += 4)
            *(float4*)(crow + j4) = make_float4(o[j4], o[j4 + 1], o[j4 + 2], o[j4 + 3]);
    }
}

// ---------------- split-K reduce -----------------------------------------
__global__ void reduce_splits(const float* __restrict__ part,
                              float* __restrict__ out,
                              int n, int nsplit, long long stride)
{
    const int i = blockIdx.x * blockDim.x + threadIdx.x;
    if (i >= n) return;
    float s = 0.f;
#pragma unroll
    for (int k = 0; k < NSPLIT; k++) s += part[(long long)k * stride + i];
    out[i] = s;
}

// ---------------- softmax over rows (warp per row), in place -------------
__global__ void softmax_rows(float* __restrict__ x, int rows, int cols)
{
    const int row = blockIdx.x * (blockDim.x / 32) + (threadIdx.x / 32);
    if (row >= rows) return;
    const int lane = threadIdx.x & 31;
    float* p = x + (long long)row * cols;

    float m = -3.0e38f;
    for (int c = lane; c < cols; c += 32) m = fmaxf(m, p[c]);
#pragma unroll
    for (int o = 16; o; o >>= 1) m = fmaxf(m, __shfl_xor_sync(0xffffffffu, m, o));

    float s = 0.f;
    for (int c = lane; c < cols; c += 32) {
        float e = __expf(p[c] - m);
        p[c] = e;
        s += e;
    }
#pragma unroll
    for (int o = 16; o; o >>= 1) s += __shfl_xor_sync(0xffffffffu, s, o);

    const float inv = 1.f / s;
    for (int c = lane; c < cols; c += 32) p[c] *= inv;
}

// ---------------- launch -------------------------------------------------
extern "C" void kernel_launch(void* const* d_in, const int* in_sizes, int n_in,
                              void* d_out, int out_size)
{
    const float* hs    = (const float*)d_in[0];
    const float* proto = (const float*)d_in[1];
    const float* lens  = (const float*)d_in[2];
    // d_in[3] = mask (bool) — unused; reconstructed from lens
    const float* Q1w = (const float*)d_in[4];
    const float* Q1b = (const float*)d_in[5];
    const float* K1w = (const float*)d_in[6];
    const float* K1b = (const float*)d_in[7];
    const float* V1w = (const float*)d_in[8];
    const float* V1b = (const float*)d_in[9];
    const float* Qw  = (const float*)d_in[10];
    const float* Qb  = (const float*)d_in[11];
    const float* Kw  = (const float*)d_in[12];
    const float* Kb  = (const float*)d_in[13];
    const float* Vw  = (const float*)d_in[14];
    const float* Vb  = (const float*)d_in[15];
    float* out = (float*)d_out;

    float *k1, *v1, *q2, *q1, *pf, *pfp, *k2, *v2, *s1, *s2;
    cudaGetSymbolAddress((void**)&k1, g_k1);
    cudaGetSymbolAddress((void**)&v1, g_v1);
    cudaGetSymbolAddress((void**)&q2, g_q2);
    cudaGetSymbolAddress((void**)&q1, g_q1);
    cudaGetSymbolAddress((void**)&pf, g_pf);
    cudaGetSymbolAddress((void**)&pfp, g_pfp);
    cudaGetSymbolAddress((void**)&k2, g_k2);
    cudaGetSymbolAddress((void**)&v2, g_v2);
    cudaGetSymbolAddress((void**)&s1, g_s1);
    cudaGetSymbolAddress((void**)&s2, g_s2);

    const dim3 blk(256);
    const int BT = BB * TT;        // 65536
    const int BP = BB * PP;        // 1024
    const long long TH = (long long)TT * HH;
    const long long PH = (long long)PP * HH;
    const long long PT = (long long)PP * TT;
    const long long TP = (long long)TT * PP;

    // q1 = proto @ Q1_w^T + Q1_b                    [64, 256]
    gemm_f2<64, 64, true><<<dim3(HH / 64, 1, 1), blk>>>(
        proto, 0, HH, Q1w, 0, HH, q1, 0, HH, HH, Q1b, 1.f, nullptr, 1, 0);

    // k1 / v1 / q2 over all tokens                  [65536, 256]
    gemm_f2<128, 128, true><<<dim3(HH / 128, BT / 128, 1), blk>>>(
        hs, 0, HH, K1w, 0, HH, k1, 0, HH, HH, K1b, 1.f, nullptr, 1, 0);
    gemm_f2<128, 128, true><<<dim3(HH / 128, BT / 128, 1), blk>>>(
        hs, 0, HH, V1w, 0, HH, v1, 0, HH, HH, V1b, 1.f, nullptr, 1, 0);
    gemm_f2<128, 128, true><<<dim3(HH / 128, BT / 128, 1), blk>>>(
        hs, 0, HH, Qw, 0, HH, q2, 0, HH, HH, Qb, 1.f, nullptr, 1, 0);

    // scores1[b,p,t] = q1 . k1 * rsqrt(len_b), masked (t >= len -> -1e9)
    gemm_f2<64, 128, true><<<dim3(TT / 128, 1, BB), blk>>>(
        q1, 0, HH, k1, TH, HH, s1, PT, TT, HH, nullptr, 1.f, lens, 1, 0);

    softmax_rows<<<BP / 8, 256>>>(s1, BP, TT);

    // pf[b] = attn1 @ v1   (split-K x8)             [64, 256] per batch
    gemm_f2<64, 64, false><<<dim3(HH / 64, 1, BB * NSPLIT), blk>>>(
        s1, PT, TT, v1, TH, HH, pfp, PH, HH, TT / NSPLIT,
        nullptr, 1.f, nullptr, NSPLIT, (long long)BB * PP * HH);
    reduce_splits<<<(BB * PP * HH + 255) / 256, 256>>>(
        pfp, pf, BB * PP * HH, NSPLIT, (long long)BB * PP * HH);

    // k2 / v2 = pf @ {K,V}_w^T + b                  [1024, 256]
    gemm_f2<64, 64, true><<<dim3(HH / 64, BP / 64, 1), blk>>>(
        pf, 0, HH, Kw, 0, HH, k2, 0, HH, HH, Kb, 1.f, nullptr, 1, 0);
    gemm_f2<64, 64, true><<<dim3(HH / 64, BP / 64, 1), blk>>>(
        pf, 0, HH, Vw, 0, HH, v2, 0, HH, HH, Vb, 1.f, nullptr, 1, 0);

    // scores2[b,t,p] = q2 . k2 / sqrt(P)
    gemm_f2<128, 64, true><<<dim3(PP / 64, TT / 128, BB), blk>>>(
        q2, TH, HH, k2, PH, HH, s2, TP, PP, HH, nullptr, 0.125f, nullptr, 1, 0);

    softmax_rows<<<BT / 8, 256>>>(s2, BT, PP);

    // out[b] = attn2 @ v2                           [4096, 256] per batch
    gemm_f2<128, 128, false><<<dim3(HH / 128, TT / 128, BB), blk>>>(
        s2, TP, PP, v2, PH, HH, out, TH, HH, PP, nullptr, 1.f, nullptr, 1, 0);
}

// round 3
// speedup vs baseline: 4.2034x; 2.2666x over previous
#include <cuda_runtime.h>
#include <cuda_bf16.h>
#include <math.h>

// Problem dims (fixed by the dataset)
#define BB 16
#define TT 4096
#define HH 256
#define PP 64

#define NSPLIT 8   // split-K factor for the pf GEMM

// ---------------- scratch (no allocation allowed) ----------------
__device__ float g_k1[BB * TT * HH];   // 64 MB
__device__ float g_v1[BB * TT * HH];   // 64 MB
__device__ float g_q2[BB * TT * HH];   // 64 MB
__device__ float g_q1[PP * HH];
__device__ float g_pf[BB * PP * HH];
__device__ float g_pfp[NSPLIT * BB * PP * HH];  // split-K partials (8 MB)
__device__ float g_k2[BB * PP * HH];
__device__ float g_v2[BB * PP * HH];
__device__ float g_s1[BB * PP * TT];   // 16 MB
__device__ float g_s2[BB * TT * PP];   // 16 MB

// ---------------- helpers ------------------------------------------------
__device__ __forceinline__ unsigned f2tf(float f) {
    unsigned r;
    asm("cvt.rna.tf32.f32 %0, %1;" : "=r"(r) : "f"(f));
    return r;
}

__device__ __forceinline__ void mma_tf32(float* c, const unsigned* a, const unsigned* b) {
    asm("mma.sync.aligned.m16n8k8.row.col.f32.tf32.tf32.f32 "
        "{%0,%1,%2,%3},{%4,%5,%6,%7},{%8,%9},{%0,%1,%2,%3};"
        : "+f"(c[0]), "+f"(c[1]), "+f"(c[2]), "+f"(c[3])
        : "r"(a[0]), "r"(a[1]), "r"(a[2]), "r"(a[3]), "r"(b[0]), "r"(b[1]));
}

// ---------------- TF32 tensor-core GEMM ----------------------------------
// C[m,n] = sum_k A[m,k] * B'[k,n]
//   BTRANS=true :  B' = B^T with B [N,K] row-major (x @ W^T pattern)
//   BTRANS=false:  B' = B     with B [K,N] row-major
// 256 threads = 8 warps laid out (BM/WM) x (BN/WN); warp tile WM x WN.
// Optional: bias[n], scale, per-batch length mask (col n >= len -> -1e9 and
// scale := rsqrt(len)), split-K (nsplit chunks of Kloop, partial strided sSplit).
#define BK 32

template<int BM, int BN, int WM, int WN, bool BTRANS>
__global__ __launch_bounds__(256, 2) void gemm_tc(
    const float* __restrict__ A, long long sA, int lda,
    const float* __restrict__ B, long long sB, int ldb,
    float* __restrict__ C, long long sC, int ldc,
    int Kloop,
    const float* __restrict__ bias, float scale,
    const float* __restrict__ lens,
    int nsplit, long long sSplit)
{
    constexpr int WCOLS = BN / WN;
    constexpr int MT = WM / 16;     // m16 tiles per warp
    constexpr int NTt = WN / 8;     // n8 tiles per warp
    constexpr int AST = BK + 4;                       // As row stride (words)
    constexpr int BST = BTRANS ? (BK + 4) : (BN + 4); // Bs row stride
    constexpr int BSZ = BTRANS ? BN * (BK + 4) : BK * (BN + 4);

    __shared__ unsigned As[BM * AST];
    __shared__ unsigned Bs[BSZ];

    const int bz = blockIdx.z;
    const int b  = bz / nsplit;
    const int ks = bz % nsplit;

    const float* Ab = A + (long long)b * sA + (long long)ks * Kloop;
    const float* Bb;
    if (BTRANS) Bb = B + (long long)b * sB + (long long)ks * Kloop;
    else        Bb = B + (long long)b * sB + (long long)ks * Kloop * ldb;
    float* Cb = C + (long long)b * sC + (long long)ks * sSplit;

    const int m0 = blockIdx.y * BM;
    const int n0 = blockIdx.x * BN;

    float maskLen = 3.0e38f;
    if (lens) {
        float L = lens[b];
        scale = rsqrtf(L);
        maskLen = L;
    }

    const int tid  = threadIdx.x;
    const int lane = tid & 31;
    const int wid  = tid >> 5;
    const int wm   = wid / WCOLS;
    const int wn   = wid % WCOLS;
    const int g    = lane >> 2;    // groupID 0..7
    const int t4   = lane & 3;     // thread-in-group 0..3

    // loader indices (A and BTRANS-B): 32 rows x 8 quad-cols per pass
    const int ar = tid >> 3;
    const int aq = (tid & 7) * 4;

    float acc[MT][NTt][4];
#pragma unroll
    for (int i = 0; i < MT; i++)
#pragma unroll
        for (int j = 0; j < NTt; j++)
#pragma unroll
            for (int q = 0; q < 4; q++) acc[i][j][q] = 0.f;

    for (int k0 = 0; k0 < Kloop; k0 += BK) {
        // ---- fill As[m][k] ----
#pragma unroll
        for (int i = 0; i < BM / 32; i++) {
            const int row = ar + 32 * i;
            const float4 v = *(const float4*)(Ab + (long long)(m0 + row) * lda + k0 + aq);
            uint4 u = make_uint4(f2tf(v.x), f2tf(v.y), f2tf(v.z), f2tf(v.w));
            *(uint4*)&As[row * AST + aq] = u;
        }
        // ---- fill Bs ----
        if (BTRANS) {
            // Bs[n][k] = B[n0+n][k0+k]
#pragma unroll
            for (int i = 0; i < BN / 32; i++) {
                const int row = ar + 32 * i;
                const float4 v = *(const float4*)(Bb + (long long)(n0 + row) * ldb + k0 + aq);
                uint4 u = make_uint4(f2tf(v.x), f2tf(v.y), f2tf(v.z), f2tf(v.w));
                *(uint4*)&Bs[row * BST + aq] = u;
            }
        } else {
            // Bs[k][n] = B[k0+k][n0+n]
            constexpr int PR = BN / 4;          // float4s per k-row
            constexpr int KR = 256 / PR;        // k-rows per pass
            const int bk = tid / PR;
            const int bn = (tid % PR) * 4;
#pragma unroll
            for (int i = 0; i < BK / KR; i++) {
                const int krow = bk + KR * i;
                const float4 v = *(const float4*)(Bb + (long long)(k0 + krow) * ldb + n0 + bn);
                uint4 u = make_uint4(f2tf(v.x), f2tf(v.y), f2tf(v.z), f2tf(v.w));
                *(uint4*)&Bs[krow * BST + bn] = u;
            }
        }
        __syncthreads();

        // ---- compute: 4 k8 substeps ----
#pragma unroll
        for (int kss = 0; kss < BK / 8; kss++) {
            const int kb = kss * 8;
            unsigned af[MT][4];
#pragma unroll
            for (int i = 0; i < MT; i++) {
                const int row = wm * WM + i * 16 + g;
                af[i][0] = As[(row)     * AST + kb + t4];
                af[i][1] = As[(row + 8) * AST + kb + t4];
                af[i][2] = As[(row)     * AST + kb + t4 + 4];
                af[i][3] = As[(row + 8) * AST + kb + t4 + 4];
            }
            unsigned bf[NTt][2];
#pragma unroll
            for (int j = 0; j < NTt; j++) {
                const int n = wn * WN + j * 8 + g;
                if (BTRANS) {
                    bf[j][0] = Bs[n * BST + kb + t4];
                    bf[j][1] = Bs[n * BST + kb + t4 + 4];
                } else {
                    bf[j][0] = Bs[(kb + t4)     * BST + n];
                    bf[j][1] = Bs[(kb + t4 + 4) * BST + n];
                }
            }
#pragma unroll
            for (int i = 0; i < MT; i++)
#pragma unroll
                for (int j = 0; j < NTt; j++)
                    mma_tf32(acc[i][j], af[i], bf[j]);
        }
        __syncthreads();
    }

    // ---- epilogue ----
#pragma unroll
    for (int i = 0; i < MT; i++) {
        const int mrow = m0 + wm * WM + i * 16 + g;
#pragma unroll
        for (int j = 0; j < NTt; j++) {
            const int ncol = n0 + wn * WN + j * 8 + 2 * t4;
            float b0 = bias ? bias[ncol]     : 0.f;
            float b1 = bias ? bias[ncol + 1] : 0.f;
            float v0 = acc[i][j][0] * scale + b0;
            float v1 = acc[i][j][1] * scale + b1;
            float v2 = acc[i][j][2] * scale + b0;
            float v3 = acc[i][j][3] * scale + b1;
            if (lens) {
                if ((float)ncol     >= maskLen) { v0 = -1e9f; v2 = -1e9f; }
                if ((float)(ncol+1) >= maskLen) { v1 = -1e9f; v3 = -1e9f; }
            }
            *(float2*)(Cb + (long long)mrow * ldc + ncol)       = make_float2(v0, v1);
            *(float2*)(Cb + (long long)(mrow + 8) * ldc + ncol) = make_float2(v2, v3);
        }
    }
}

// ---------------- split-K reduce -----------------------------------------
__global__ void reduce_splits(const float* __restrict__ part,
                              float* __restrict__ out,
                              int n, long long stride)
{
    const int i = blockIdx.x * blockDim.x + threadIdx.x;
    if (i >= n) return;
    float s = 0.f;
#pragma unroll
    for (int k = 0; k < NSPLIT; k++) s += part[(long long)k * stride + i];
    out[i] = s;
}

// ---------------- softmax over rows (warp per row), in place -------------
__global__ void softmax_rows(float* __restrict__ x, int rows, int cols)
{
    const int row = blockIdx.x * (blockDim.x / 32) + (threadIdx.x / 32);
    if (row >= rows) return;
    const int lane = threadIdx.x & 31;
    float* p = x + (long long)row * cols;

    float m = -3.0e38f;
    for (int c = lane; c < cols; c += 32) m = fmaxf(m, p[c]);
#pragma unroll
    for (int o = 16; o; o >>= 1) m = fmaxf(m, __shfl_xor_sync(0xffffffffu, m, o));

    float s = 0.f;
    for (int c = lane; c < cols; c += 32) {
        float e = __expf(p[c] - m);
        p[c] = e;
        s += e;
    }
#pragma unroll
    for (int o = 16; o; o >>= 1) s += __shfl_xor_sync(0xffffffffu, s, o);

    const float inv = 1.f / s;
    for (int c = lane; c < cols; c += 32) p[c] *= inv;
}

// ---------------- launch -------------------------------------------------
extern "C" void kernel_launch(void* const* d_in, const int* in_sizes, int n_in,
                              void* d_out, int out_size)
{
    const float* hs    = (const float*)d_in[0];
    const float* proto = (const float*)d_in[1];
    const float* lens  = (const float*)d_in[2];
    // d_in[3] = mask (bool) — unused; reconstructed from lens
    const float* Q1w = (const float*)d_in[4];
    const float* Q1b = (const float*)d_in[5];
    const float* K1w = (const float*)d_in[6];
    const float* K1b = (const float*)d_in[7];
    const float* V1w = (const float*)d_in[8];
    const float* V1b = (const float*)d_in[9];
    const float* Qw  = (const float*)d_in[10];
    const float* Qb  = (const float*)d_in[11];
    const float* Kw  = (const float*)d_in[12];
    const float* Kb  = (const float*)d_in[13];
    const float* Vw  = (const float*)d_in[14];
    const float* Vb  = (const float*)d_in[15];
    float* out = (float*)d_out;

    float *k1, *v1, *q2, *q1, *pf, *pfp, *k2, *v2, *s1, *s2;
    cudaGetSymbolAddress((void**)&k1, g_k1);
    cudaGetSymbolAddress((void**)&v1, g_v1);
    cudaGetSymbolAddress((void**)&q2, g_q2);
    cudaGetSymbolAddress((void**)&q1, g_q1);
    cudaGetSymbolAddress((void**)&pf, g_pf);
    cudaGetSymbolAddress((void**)&pfp, g_pfp);
    cudaGetSymbolAddress((void**)&k2, g_k2);
    cudaGetSymbolAddress((void**)&v2, g_v2);
    cudaGetSymbolAddress((void**)&s1, g_s1);
    cudaGetSymbolAddress((void**)&s2, g_s2);

    const dim3 blk(256);
    const int BT = BB * TT;        // 65536
    const int BP = BB * PP;        // 1024
    const long long TH = (long long)TT * HH;
    const long long PH = (long long)PP * HH;
    const long long PT = (long long)PP * TT;
    const long long TP = (long long)TT * PP;

    // q1 = proto @ Q1_w^T + Q1_b                    [64, 256]
    gemm_tc<64, 128, 32, 32, true><<<dim3(HH / 128, 1, 1), blk>>>(
        proto, 0, HH, Q1w, 0, HH, q1, 0, HH, HH, Q1b, 1.f, nullptr, 1, 0);

    // k1 / v1 / q2 over all tokens                  [65536, 256]
    gemm_tc<128, 128, 64, 32, true><<<dim3(HH / 128, BT / 128, 1), blk>>>(
        hs, 0, HH, K1w, 0, HH, k1, 0, HH, HH, K1b, 1.f, nullptr, 1, 0);
    gemm_tc<128, 128, 64, 32, true><<<dim3(HH / 128, BT / 128, 1), blk>>>(
        hs, 0, HH, V1w, 0, HH, v1, 0, HH, HH, V1b, 1.f, nullptr, 1, 0);
    gemm_tc<128, 128, 64, 32, true><<<dim3(HH / 128, BT / 128, 1), blk>>>(
        hs, 0, HH, Qw, 0, HH, q2, 0, HH, HH, Qb, 1.f, nullptr, 1, 0);

    // scores1[b,p,t] = q1 . k1 * rsqrt(len_b), masked (t >= len -> -1e9)
    gemm_tc<64, 128, 32, 32, true><<<dim3(TT / 128, 1, BB), blk>>>(
        q1, 0, HH, k1, TH, HH, s1, PT, TT, HH, nullptr, 1.f, lens, 1, 0);

    softmax_rows<<<BP / 8, 256>>>(s1, BP, TT);

    // pf[b] = attn1 @ v1   (split-K x8)             [64, 256] per batch
    gemm_tc<64, 64, 32, 16, false><<<dim3(HH / 64, 1, BB * NSPLIT), blk>>>(
        s1, PT, TT, v1, TH, HH, pfp, PH, HH, TT / NSPLIT,
        nullptr, 1.f, nullptr, NSPLIT, (long long)BB * PP * HH);
    reduce_splits<<<(BB * PP * HH + 255) / 256, 256>>>(
        pfp, pf, BB * PP * HH, (long long)BB * PP * HH);

    // k2 / v2 = pf @ {K,V}_w^T + b                  [1024, 256]
    gemm_tc<64, 128, 32, 32, true><<<dim3(HH / 128, BP / 64, 1), blk>>>(
        pf, 0, HH, Kw, 0, HH, k2, 0, HH, HH, Kb, 1.f, nullptr, 1, 0);
    gemm_tc<64, 128, 32, 32, true><<<dim3(HH / 128, BP / 64, 1), blk>>>(
        pf, 0, HH, Vw, 0, HH, v2, 0, HH, HH, Vb, 1.f, nullptr, 1, 0);

    // scores2[b,t,p] = q2 . k2 / sqrt(P)
    gemm_tc<128, 64, 32, 32, true><<<dim3(PP / 64, TT / 128, BB), blk>>>(
        q2, TH, HH, k2, PH, HH, s2, TP, PP, HH, nullptr, 0.125f, nullptr, 1, 0);

    softmax_rows<<<BT / 8, 256>>>(s2, BT, PP);

    // out[b] = attn2 @ v2                           [4096, 256] per batch
    gemm_tc<128, 128, 64, 32, false><<<dim3(HH / 128, TT / 128, BB), blk>>>(
        s2, TP, PP, v2, PH, HH, out, TH, HH, PP, nullptr, 1.f, nullptr, 1, 0);
}

// round 7
// speedup vs baseline: 4.6365x; 1.1030x over previous
#include <cuda_runtime.h>
#include <cuda_bf16.h>
#include <math.h>

// Problem dims (fixed by the dataset)
#define BB 16
#define TT 4096
#define HH 256
#define PP 64

#define NSPLIT 8   // split-K factor for the pf GEMM

// ---------------- scratch (no allocation allowed) ----------------
__device__ float g_k1[BB * TT * HH];   // 64 MB
__device__ float g_v1[BB * TT * HH];   // 64 MB
__device__ float g_q2[BB * TT * HH];   // 64 MB
__device__ float g_q1[PP * HH];
__device__ float g_pf[BB * PP * HH];
__device__ float g_pfp[NSPLIT * BB * PP * HH];  // split-K partials (8 MB)
__device__ float g_k2[BB * PP * HH];
__device__ float g_v2[BB * PP * HH];
__device__ float g_s1[BB * PP * TT];   // 16 MB
__device__ float g_s2[BB * TT * PP];   // 16 MB

// ---------------- helpers ------------------------------------------------
__device__ __forceinline__ void mma_tf32(float* c, const unsigned* a, const unsigned* b) {
    asm("mma.sync.aligned.m16n8k8.row.col.f32.tf32.tf32.f32 "
        "{%0,%1,%2,%3},{%4,%5,%6,%7},{%8,%9},{%0,%1,%2,%3};"
        : "+f"(c[0]), "+f"(c[1]), "+f"(c[2]), "+f"(c[3])
        : "r"(a[0]), "r"(a[1]), "r"(a[2]), "r"(a[3]), "r"(b[0]), "r"(b[1]));
}

// Round-to-nearest for tf32: MMA truncates the low 13 mantissa bits, so adding
// half an ulp (0x1000) of the kept field implements RNA in one IADD.
__device__ __forceinline__ unsigned rnd13(unsigned u) { return u + 0x1000u; }

__device__ __forceinline__ void cpa16(void* dst, const void* src) {
    unsigned d = (unsigned)__cvta_generic_to_shared(dst);
    asm volatile("cp.async.cg.shared.global [%0], [%1], 16;" :: "r"(d), "l"(src));
}
__device__ __forceinline__ void cp_commit() {
    asm volatile("cp.async.commit_group;");
}
template<int N>
__device__ __forceinline__ void cp_wait() {
    asm volatile("cp.async.wait_group %0;" :: "n"(N));
}

// ---------------- TF32 tensor-core GEMM, cp.async double-buffered --------
// C[m,n] = sum_k A[m,k] * B'[k,n]
//   BTRANS=true :  B' = B^T with B [N,K] row-major (x @ W^T pattern)
//   BTRANS=false:  B' = B     with B [K,N] row-major
// 256 threads = 8 warps laid out (BM/WM) x (BN/WN); warp tile WM x WN.
// A (and BTRANS-B) tiles stored [row][k] with XOR quad swizzle; NN-B stored
// [k][n] with +8 padding. fp32 bits rounded (rnd13) at fragment load.
// Tile buffers live in DYNAMIC shared memory (static cap is 48 KB).
#define BK 32

template<int BM, int BN, bool BTRANS>
struct SmemSizes {
    static constexpr int AWORDS = BM * BK;
    static constexpr int BSTNN  = BN + 8;
    static constexpr int BWORDS = BTRANS ? BN * BK : BK * BSTNN;
    static constexpr int BYTES  = (2 * AWORDS + 2 * BWORDS) * 4;
};

template<int BM, int BN, int WM, int WN, bool BTRANS>
__global__ __launch_bounds__(256, 2) void gemm_tc(
    const float* __restrict__ A, long long sA, int lda,
    const float* __restrict__ B, long long sB, int ldb,
    float* __restrict__ C, long long sC, int ldc,
    int Kloop,
    const float* __restrict__ bias, float scale,
    const float* __restrict__ lens,
    int nsplit, long long sSplit)
{
    constexpr int WCOLS = BN / WN;
    constexpr int MT  = WM / 16;    // m16 tiles per warp
    constexpr int NTt = WN / 8;     // n8 tiles per warp
    constexpr int AWORDS = SmemSizes<BM, BN, BTRANS>::AWORDS;
    constexpr int BSTNN  = SmemSizes<BM, BN, BTRANS>::BSTNN;
    constexpr int BWORDS = SmemSizes<BM, BN, BTRANS>::BWORDS;

    extern __shared__ unsigned smem_dyn[];
    unsigned* As[2] = { smem_dyn, smem_dyn + AWORDS };
    unsigned* Bs[2] = { smem_dyn + 2 * AWORDS, smem_dyn + 2 * AWORDS + BWORDS };

    const int bz = blockIdx.z;
    const int b  = bz / nsplit;
    const int ks = bz % nsplit;

    const float* Ab = A + (long long)b * sA + (long long)ks * Kloop;
    const float* Bb;
    if (BTRANS) Bb = B + (long long)b * sB + (long long)ks * Kloop;
    else        Bb = B + (long long)b * sB + (long long)ks * Kloop * ldb;
    float* Cb = C + (long long)b * sC + (long long)ks * sSplit;

    const int m0 = blockIdx.y * BM;
    const int n0 = blockIdx.x * BN;

    float maskLen = 3.0e38f;
    if (lens) {
        float L = lens[b];
        scale = rsqrtf(L);
        maskLen = L;
    }

    const int tid  = threadIdx.x;
    const int lane = tid & 31;
    const int wid  = tid >> 5;
    const int wm   = wid / WCOLS;
    const int wn   = wid % WCOLS;
    const int g    = lane >> 2;    // groupID 0..7
    const int t4   = lane & 3;     // thread-in-group 0..3

    // loader indices for swizzled [row][k] tiles: 32 rows x 8 quads per pass
    const int ar = tid >> 3;       // 0..31
    const int aq = tid & 7;        // quad 0..7

    auto loadA = [&](int buf, int k0) {
#pragma unroll
        for (int i = 0; i < BM / 32; i++) {
            const int row = ar + 32 * i;
            cpa16(&As[buf][row * BK + ((aq ^ (row & 7)) << 2)],
                  Ab + (long long)(m0 + row) * lda + k0 + (aq << 2));
        }
    };
    auto loadB = [&](int buf, int k0) {
        if (BTRANS) {
#pragma unroll
            for (int i = 0; i < BN / 32; i++) {
                const int row = ar + 32 * i;
                cpa16(&Bs[buf][row * BK + ((aq ^ (row & 7)) << 2)],
                      Bb + (long long)(n0 + row) * ldb + k0 + (aq << 2));
            }
        } else {
            constexpr int QPR = BN / 4;          // quads per k-row
            constexpr int RPP = 256 / QPR;       // k-rows per pass
            const int bk = tid / QPR;
            const int bq = tid % QPR;
#pragma unroll
            for (int i = 0; i < BK / RPP; i++) {
                const int krow = bk + RPP * i;
                cpa16(&Bs[buf][krow * BSTNN + bq * 4],
                      Bb + (long long)(k0 + krow) * ldb + n0 + bq * 4);
            }
        }
    };

    float acc[MT][NTt][4];
#pragma unroll
    for (int i = 0; i < MT; i++)
#pragma unroll
        for (int j = 0; j < NTt; j++)
#pragma unroll
            for (int q = 0; q < 4; q++) acc[i][j][q] = 0.f;

    const int nIter = Kloop / BK;
    loadA(0, 0);
    loadB(0, 0);
    cp_commit();

    for (int it = 0; it < nIter; it++) {
        const int cb = it & 1;
        if (it + 1 < nIter) {
            loadA(cb ^ 1, (it + 1) * BK);
            loadB(cb ^ 1, (it + 1) * BK);
            cp_commit();
            cp_wait<1>();
        } else {
            cp_wait<0>();
        }
        __syncthreads();

#pragma unroll
        for (int kss = 0; kss < BK / 8; kss++) {
            const int kb = kss * 8;
            const int q0 = kb >> 2;
            unsigned af[MT][4];
#pragma unroll
            for (int i = 0; i < MT; i++) {
                const int row = wm * WM + i * 16 + g;   // row & 7 == g
                const int p0 = (q0 ^ g) << 2;
                const int p1 = ((q0 + 1) ^ g) << 2;
                af[i][0] = rnd13(As[cb][(row)     * BK + p0 + t4]);
                af[i][1] = rnd13(As[cb][(row + 8) * BK + p0 + t4]);
                af[i][2] = rnd13(As[cb][(row)     * BK + p1 + t4]);
                af[i][3] = rnd13(As[cb][(row + 8) * BK + p1 + t4]);
            }
            unsigned bf[NTt][2];
#pragma unroll
            for (int j = 0; j < NTt; j++) {
                const int n = wn * WN + j * 8 + g;      // n & 7 == g
                if (BTRANS) {
                    const int p0 = (q0 ^ g) << 2;
                    const int p1 = ((q0 + 1) ^ g) << 2;
                    bf[j][0] = rnd13(Bs[cb][n * BK + p0 + t4]);
                    bf[j][1] = rnd13(Bs[cb][n * BK + p1 + t4]);
                } else {
                    bf[j][0] = rnd13(Bs[cb][(kb + t4)     * BSTNN + n]);
                    bf[j][1] = rnd13(Bs[cb][(kb + t4 + 4) * BSTNN + n]);
                }
            }
#pragma unroll
            for (int i = 0; i < MT; i++)
#pragma unroll
                for (int j = 0; j < NTt; j++)
                    mma_tf32(acc[i][j], af[i], bf[j]);
        }
        __syncthreads();
    }

    // ---- epilogue ----
#pragma unroll
    for (int i = 0; i < MT; i++) {
        const int mrow = m0 + wm * WM + i * 16 + g;
#pragma unroll
        for (int j = 0; j < NTt; j++) {
            const int ncol = n0 + wn * WN + j * 8 + 2 * t4;
            float b0 = bias ? bias[ncol]     : 0.f;
            float b1 = bias ? bias[ncol + 1] : 0.f;
            float v0 = acc[i][j][0] * scale + b0;
            float v1 = acc[i][j][1] * scale + b1;
            float v2 = acc[i][j][2] * scale + b0;
            float v3 = acc[i][j][3] * scale + b1;
            if (lens) {
                if ((float)ncol     >= maskLen) { v0 = -1e9f; v2 = -1e9f; }
                if ((float)(ncol+1) >= maskLen) { v1 = -1e9f; v3 = -1e9f; }
            }
            *(float2*)(Cb + (long long)mrow * ldc + ncol)       = make_float2(v0, v1);
            *(float2*)(Cb + (long long)(mrow + 8) * ldc + ncol) = make_float2(v2, v3);
        }
    }
}

// ---------------- split-K reduce -----------------------------------------
__global__ void reduce_splits(const float* __restrict__ part,
                              float* __restrict__ out,
                              int n, long long stride)
{
    const int i = blockIdx.x * blockDim.x + threadIdx.x;
    if (i >= n) return;
    float s = 0.f;
#pragma unroll
    for (int k = 0; k < NSPLIT; k++) s += part[(long long)k * stride + i];
    out[i] = s;
}

// ---------------- softmax over rows (warp per row), in place -------------
__global__ void softmax_rows(float* __restrict__ x, int rows, int cols)
{
    const int row = blockIdx.x * (blockDim.x / 32) + (threadIdx.x / 32);
    if (row >= rows) return;
    const int lane = threadIdx.x & 31;
    float* p = x + (long long)row * cols;

    float m = -3.0e38f;
    for (int c = lane; c < cols; c += 32) m = fmaxf(m, p[c]);
#pragma unroll
    for (int o = 16; o; o >>= 1) m = fmaxf(m, __shfl_xor_sync(0xffffffffu, m, o));

    float s = 0.f;
    for (int c = lane; c < cols; c += 32) {
        float e = __expf(p[c] - m);
        p[c] = e;
        s += e;
    }
#pragma unroll
    for (int o = 16; o; o >>= 1) s += __shfl_xor_sync(0xffffffffu, s, o);

    const float inv = 1.f / s;
    for (int c = lane; c < cols; c += 32) p[c] *= inv;
}

// ---------------- launch helper ------------------------------------------
template<int BM, int BN, int WM, int WN, bool BTRANS>
static void launch_gemm(dim3 grid,
                        const float* A, long long sA, int lda,
                        const float* B, long long sB, int ldb,
                        float* C, long long sC, int ldc,
                        int Kloop,
                        const float* bias, float scale,
                        const float* lens,
                        int nsplit, long long sSplit)
{
    constexpr int SMEM = SmemSizes<BM, BN, BTRANS>::BYTES;
    cudaFuncSetAttribute(gemm_tc<BM, BN, WM, WN, BTRANS>,
                         cudaFuncAttributeMaxDynamicSharedMemorySize, SMEM);
    gemm_tc<BM, BN, WM, WN, BTRANS><<<grid, 256, SMEM>>>(
        A, sA, lda, B, sB, ldb, C, sC, ldc, Kloop, bias, scale, lens, nsplit, sSplit);
}

// ---------------- launch -------------------------------------------------
extern "C" void kernel_launch(void* const* d_in, const int* in_sizes, int n_in,
                              void* d_out, int out_size)
{
    const float* hs    = (const float*)d_in[0];
    const float* proto = (const float*)d_in[1];
    const float* lens  = (const float*)d_in[2];
    // d_in[3] = mask (bool) — unused; reconstructed from lens
    const float* Q1w = (const float*)d_in[4];
    const float* Q1b = (const float*)d_in[5];
    const float* K1w = (const float*)d_in[6];
    const float* K1b = (const float*)d_in[7];
    const float* V1w = (const float*)d_in[8];
    const float* V1b = (const float*)d_in[9];
    const float* Qw  = (const float*)d_in[10];
    const float* Qb  = (const float*)d_in[11];
    const float* Kw  = (const float*)d_in[12];
    const float* Kb  = (const float*)d_in[13];
    const float* Vw  = (const float*)d_in[14];
    const float* Vb  = (const float*)d_in[15];
    float* out = (float*)d_out;

    float *k1, *v1, *q2, *q1, *pf, *pfp, *k2, *v2, *s1, *s2;
    cudaGetSymbolAddress((void**)&k1, g_k1);
    cudaGetSymbolAddress((void**)&v1, g_v1);
    cudaGetSymbolAddress((void**)&q2, g_q2);
    cudaGetSymbolAddress((void**)&q1, g_q1);
    cudaGetSymbolAddress((void**)&pf, g_pf);
    cudaGetSymbolAddress((void**)&pfp, g_pfp);
    cudaGetSymbolAddress((void**)&k2, g_k2);
    cudaGetSymbolAddress((void**)&v2, g_v2);
    cudaGetSymbolAddress((void**)&s1, g_s1);
    cudaGetSymbolAddress((void**)&s2, g_s2);

    const int BT = BB * TT;        // 65536
    const int BP = BB * PP;        // 1024
    const long long TH = (long long)TT * HH;
    const long long PH = (long long)PP * HH;
    const long long PT = (long long)PP * TT;
    const long long TP = (long long)TT * PP;

    // q1 = proto @ Q1_w^T + Q1_b                    [64, 256]
    launch_gemm<64, 128, 32, 32, true>(dim3(HH / 128, 1, 1),
        proto, 0, HH, Q1w, 0, HH, q1, 0, HH, HH, Q1b, 1.f, nullptr, 1, 0);

    // k1 / v1 / q2 over all tokens                  [65536, 256]
    launch_gemm<128, 128, 64, 32, true>(dim3(HH / 128, BT / 128, 1),
        hs, 0, HH, K1w, 0, HH, k1, 0, HH, HH, K1b, 1.f, nullptr, 1, 0);
    launch_gemm<128, 128, 64, 32, true>(dim3(HH / 128, BT / 128, 1),
        hs, 0, HH, V1w, 0, HH, v1, 0, HH, HH, V1b, 1.f, nullptr, 1, 0);
    launch_gemm<128, 128, 64, 32, true>(dim3(HH / 128, BT / 128, 1),
        hs, 0, HH, Qw, 0, HH, q2, 0, HH, HH, Qb, 1.f, nullptr, 1, 0);

    // scores1[b,p,t] = q1 . k1 * rsqrt(len_b), masked (t >= len -> -1e9)
    launch_gemm<64, 128, 32, 32, true>(dim3(TT / 128, 1, BB),
        q1, 0, HH, k1, TH, HH, s1, PT, TT, HH, nullptr, 1.f, lens, 1, 0);

    softmax_rows<<<BP / 8, 256>>>(s1, BP, TT);

    // pf[b] = attn1 @ v1   (split-K x8)             [64, 256] per batch
    launch_gemm<64, 64, 32, 16, false>(dim3(HH / 64, 1, BB * NSPLIT),
        s1, PT, TT, v1, TH, HH, pfp, PH, HH, TT / NSPLIT,
        nullptr, 1.f, nullptr, NSPLIT, (long long)BB * PP * HH);
    reduce_splits<<<(BB * PP * HH + 255) / 256, 256>>>(
        pfp, pf, BB * PP * HH, (long long)BB * PP * HH);

    // k2 / v2 = pf @ {K,V}_w^T + b                  [1024, 256]
    launch_gemm<64, 128, 32, 32, true>(dim3(HH / 128, BP / 64, 1),
        pf, 0, HH, Kw, 0, HH, k2, 0, HH, HH, Kb, 1.f, nullptr, 1, 0);
    launch_gemm<64, 128, 32, 32, true>(dim3(HH / 128, BP / 64, 1),
        pf, 0, HH, Vw, 0, HH, v2, 0, HH, HH, Vb, 1.f, nullptr, 1, 0);

    // scores2[b,t,p] = q2 . k2 / sqrt(P)
    launch_gemm<128, 64, 32, 32, true>(dim3(PP / 64, TT / 128, BB),
        q2, TH, HH, k2, PH, HH, s2, TP, PP, HH, nullptr, 0.125f, nullptr, 1, 0);

    softmax_rows<<<BT / 8, 256>>>(s2, BT, PP);

    // out[b] = attn2 @ v2                           [4096, 256] per batch
    launch_gemm<128, 128, 64, 32, false>(dim3(HH / 128, TT / 128, BB),
        s2, TP, PP, v2, PH, HH, out, TH, HH, PP, nullptr, 1.f, nullptr, 1, 0);
}

// round 8
// speedup vs baseline: 5.7082x; 1.2311x over previous
#include <cuda_runtime.h>
#include <cuda_bf16.h>
#include <math.h>

// Problem dims (fixed by the dataset)
#define BB 16
#define TT 4096
#define HH 256
#define PP 64

#define NSPLIT 8   // split-K factor for the pf GEMM

// ---------------- scratch (no allocation allowed) ----------------
__device__ float g_k1[BB * TT * HH];   // 64 MB
__device__ float g_v1[BB * TT * HH];   // 64 MB
__device__ float g_q2[BB * TT * HH];   // 64 MB
__device__ float g_q1[PP * HH];
__device__ float g_pf[BB * PP * HH];
__device__ float g_pfp[NSPLIT * BB * PP * HH];  // split-K partials (8 MB)
__device__ float g_k2[BB * PP * HH];
__device__ float g_v2[BB * PP * HH];
__device__ float g_s1[BB * PP * TT];   // 16 MB
__device__ float g_s2[BB * TT * PP];   // 16 MB

// ---------------- helpers ------------------------------------------------
__device__ __forceinline__ void mma_tf32(float* c, const unsigned* a, const unsigned* b) {
    asm("mma.sync.aligned.m16n8k8.row.col.f32.tf32.tf32.f32 "
        "{%0,%1,%2,%3},{%4,%5,%6,%7},{%8,%9},{%0,%1,%2,%3};"
        : "+f"(c[0]), "+f"(c[1]), "+f"(c[2]), "+f"(c[3])
        : "r"(a[0]), "r"(a[1]), "r"(a[2]), "r"(a[3]), "r"(b[0]), "r"(b[1]));
}

// Round-to-nearest for tf32: MMA truncates the low 13 mantissa bits, so adding
// half an ulp (0x1000) of the kept field implements RNA in one IADD.
__device__ __forceinline__ unsigned rnd13(unsigned u) { return u + 0x1000u; }

__device__ __forceinline__ void ldsm_x4(unsigned& r0, unsigned& r1,
                                        unsigned& r2, unsigned& r3, unsigned addr) {
    asm volatile("ldmatrix.sync.aligned.m8n8.x4.shared.b16 {%0,%1,%2,%3}, [%4];"
                 : "=r"(r0), "=r"(r1), "=r"(r2), "=r"(r3) : "r"(addr));
}

__device__ __forceinline__ void cpa16s(unsigned dst, const void* src) {
    asm volatile("cp.async.cg.shared.global [%0], [%1], 16;" :: "r"(dst), "l"(src));
}
__device__ __forceinline__ void cp_commit() {
    asm volatile("cp.async.commit_group;");
}
template<int N>
__device__ __forceinline__ void cp_wait() {
    asm volatile("cp.async.wait_group %0;" :: "n"(N));
}

// ---------------- TF32 tensor-core GEMM, 3-stage cp.async + ldmatrix -----
// C[m,n] = sum_k A[m,k] * B'[k,n]
//   BTRANS=true :  B' = B^T with B [N,K] row-major (x @ W^T pattern)
//   BTRANS=false:  B' = B     with B [K,N] row-major
// 256 threads = 8 warps laid out (BM/WM) x (BN/WN); warp tile WM x WN.
// A (and BTRANS-B) tiles stored [row][k] with XOR quad swizzle, fragments
// loaded via ldmatrix.x4; NN-B stored [k][n] with +8 padding, scalar loads.
// fp32 bits rounded (rnd13) in registers -> exact cvt.rna.tf32 semantics.
#define BK 32
#define NSTG 3

template<int BM, int BN, bool BTRANS>
struct SmemSizes {
    static constexpr int AWORDS = BM * BK;
    static constexpr int BSTNN  = BN + 8;
    static constexpr int BWORDS = BTRANS ? BN * BK : BK * BSTNN;
    static constexpr int STW    = AWORDS + BWORDS;     // words per stage
    static constexpr int BYTES  = NSTG * STW * 4;
};

template<int BM, int BN, int WM, int WN, bool BTRANS>
__global__ __launch_bounds__(256, 2) void gemm_tc(
    const float* __restrict__ A, long long sA, int lda,
    const float* __restrict__ B, long long sB, int ldb,
    float* __restrict__ C, long long sC, int ldc,
    int Kloop,
    const float* __restrict__ bias, float scale,
    const float* __restrict__ lens,
    int nsplit, long long sSplit)
{
    constexpr int WCOLS = BN / WN;
    constexpr int MT  = WM / 16;    // m16 tiles per warp
    constexpr int NTt = WN / 8;     // n8 tiles per warp
    constexpr int NJ  = NTt / 2;    // ldmatrix.x4 covers 2 n8 tiles
    constexpr int AWORDS = SmemSizes<BM, BN, BTRANS>::AWORDS;
    constexpr int BSTNN  = SmemSizes<BM, BN, BTRANS>::BSTNN;
    constexpr int STW    = SmemSizes<BM, BN, BTRANS>::STW;

    extern __shared__ unsigned smem_dyn[];
    const unsigned sbase = (unsigned)__cvta_generic_to_shared(smem_dyn);

    const int bz = blockIdx.z;
    const int b  = bz / nsplit;
    const int ks = bz % nsplit;

    const float* Ab = A + (long long)b * sA + (long long)ks * Kloop;
    const float* Bb;
    if (BTRANS) Bb = B + (long long)b * sB + (long long)ks * Kloop;
    else        Bb = B + (long long)b * sB + (long long)ks * Kloop * ldb;
    float* Cb = C + (long long)b * sC + (long long)ks * sSplit;

    const int m0 = blockIdx.y * BM;
    const int n0 = blockIdx.x * BN;

    float maskLen = 3.0e38f;
    if (lens) {
        float L = lens[b];
        scale = rsqrtf(L);
        maskLen = L;
    }

    const int tid  = threadIdx.x;
    const int lane = tid & 31;
    const int wid  = tid >> 5;
    const int wm   = wid / WCOLS;
    const int wn   = wid % WCOLS;
    const int g    = lane >> 2;     // groupID 0..7
    const int t4   = lane & 3;      // thread-in-group 0..3
    const int l7   = lane & 7;
    const int lr15 = lane & 15;
    const int hb   = lane >> 4;         // 0/1 : quad-select for A ldmatrix
    const int qb   = (lane >> 3) & 1;   // 0/1 : quad-select for B ldmatrix

    // loader indices for swizzled [row][k] tiles: 32 rows x 8 quads per pass
    const int ar = tid >> 3;        // 0..31
    const int aq = tid & 7;         // quad 0..7

    auto loadA = [&](int s, int k0) {
        const unsigned abase = sbase + (s * STW) * 4;
#pragma unroll
        for (int i = 0; i < BM / 32; i++) {
            const int row = ar + 32 * i;
            cpa16s(abase + (row * BK + ((aq ^ (row & 7)) << 2)) * 4,
                   Ab + (long long)(m0 + row) * lda + k0 + (aq << 2));
        }
    };
    auto loadB = [&](int s, int k0) {
        const unsigned bbase = sbase + (s * STW + AWORDS) * 4;
        if (BTRANS) {
#pragma unroll
            for (int i = 0; i < BN / 32; i++) {
                const int row = ar + 32 * i;
                cpa16s(bbase + (row * BK + ((aq ^ (row & 7)) << 2)) * 4,
                       Bb + (long long)(n0 + row) * ldb + k0 + (aq << 2));
            }
        } else {
            constexpr int QPR = BN / 4;          // quads per k-row
            constexpr int RPP = 256 / QPR;       // k-rows per pass
            const int bk = tid / QPR;
            const int bq = tid % QPR;
#pragma unroll
            for (int i = 0; i < BK / RPP; i++) {
                const int krow = bk + RPP * i;
                cpa16s(bbase + (krow * BSTNN + bq * 4) * 4,
                       Bb + (long long)(k0 + krow) * ldb + n0 + bq * 4);
            }
        }
    };

    // per-lane ldmatrix row offsets (stage-independent, bytes)
    unsigned aRowOff[MT];
#pragma unroll
    for (int i = 0; i < MT; i++)
        aRowOff[i] = (wm * WM + i * 16 + lr15) * BK * 4;
    unsigned bRowOff[NJ];
    if (BTRANS) {
#pragma unroll
        for (int jj = 0; jj < NJ; jj++)
            bRowOff[jj] = (wn * WN + jj * 16 + hb * 8 + l7) * BK * 4;
    }

    float acc[MT][NTt][4];
#pragma unroll
    for (int i = 0; i < MT; i++)
#pragma unroll
        for (int j = 0; j < NTt; j++)
#pragma unroll
            for (int q = 0; q < 4; q++) acc[i][j][q] = 0.f;

    const int nIter = Kloop / BK;

    // prologue: prefetch stages 0,1 (always 2 committed groups)
    loadA(0, 0);
    loadB(0, 0);
    cp_commit();
    if (nIter > 1) { loadA(1, BK); loadB(1, BK); }
    cp_commit();

    int cb = 0;
    for (int it = 0; it < nIter; it++) {
        if (it + 2 < nIter) {
            const int nbuf = (cb == 0) ? 2 : cb - 1;   // (cb+2) mod 3
            loadA(nbuf, (it + 2) * BK);
            loadB(nbuf, (it + 2) * BK);
        }
        cp_commit();          // may be an empty group (keeps FIFO uniform)
        cp_wait<2>();
        __syncthreads();

        const unsigned aSt = sbase + (cb * STW) * 4;
        const unsigned bSt = aSt + AWORDS * 4;
        const unsigned* BsNN = smem_dyn + cb * STW + AWORDS;

#pragma unroll
        for (int kss = 0; kss < BK / 8; kss++) {
            const int q0 = kss * 2;
            unsigned af[MT][4];
#pragma unroll
            for (int i = 0; i < MT; i++) {
                ldsm_x4(af[i][0], af[i][1], af[i][2], af[i][3],
                        aSt + aRowOff[i] + (unsigned)((((q0 + hb) ^ l7)) << 4));
                af[i][0] = rnd13(af[i][0]); af[i][1] = rnd13(af[i][1]);
                af[i][2] = rnd13(af[i][2]); af[i][3] = rnd13(af[i][3]);
            }
            unsigned bf[NTt][2];
            if (BTRANS) {
#pragma unroll
                for (int jj = 0; jj < NJ; jj++) {
                    unsigned w0, w1, w2, w3;
                    ldsm_x4(w0, w1, w2, w3,
                            bSt + bRowOff[jj] + (unsigned)((((q0 + qb) ^ l7)) << 4));
                    bf[2 * jj][0]     = rnd13(w0);
                    bf[2 * jj][1]     = rnd13(w1);
                    bf[2 * jj + 1][0] = rnd13(w2);
                    bf[2 * jj + 1][1] = rnd13(w3);
                }
            } else {
                const int kb = kss * 8;
#pragma unroll
                for (int j = 0; j < NTt; j++) {
                    const int n = wn * WN + j * 8 + g;
                    bf[j][0] = rnd13(BsNN[(kb + t4)     * BSTNN + n]);
                    bf[j][1] = rnd13(BsNN[(kb + t4 + 4) * BSTNN + n]);
                }
            }
#pragma unroll
            for (int i = 0; i < MT; i++)
#pragma unroll
                for (int j = 0; j < NTt; j++)
                    mma_tf32(acc[i][j], af[i], bf[j]);
        }
        __syncthreads();
        cb = (cb == 2) ? 0 : cb + 1;
    }

    // ---- epilogue ----
#pragma unroll
    for (int i = 0; i < MT; i++) {
        const int mrow = m0 + wm * WM + i * 16 + g;
#pragma unroll
        for (int j = 0; j < NTt; j++) {
            const int ncol = n0 + wn * WN + j * 8 + 2 * t4;
            float b0 = bias ? bias[ncol]     : 0.f;
            float b1 = bias ? bias[ncol + 1] : 0.f;
            float v0 = acc[i][j][0] * scale + b0;
            float v1 = acc[i][j][1] * scale + b1;
            float v2 = acc[i][j][2] * scale + b0;
            float v3 = acc[i][j][3] * scale + b1;
            if (lens) {
                if ((float)ncol     >= maskLen) { v0 = -1e9f; v2 = -1e9f; }
                if ((float)(ncol+1) >= maskLen) { v1 = -1e9f; v3 = -1e9f; }
            }
            *(float2*)(Cb + (long long)mrow * ldc + ncol)       = make_float2(v0, v1);
            *(float2*)(Cb + (long long)(mrow + 8) * ldc + ncol) = make_float2(v2, v3);
        }
    }
}

// ---------------- split-K reduce -----------------------------------------
__global__ void reduce_splits(const float* __restrict__ part,
                              float* __restrict__ out,
                              int n, long long stride)
{
    const int i = blockIdx.x * blockDim.x + threadIdx.x;
    if (i >= n) return;
    float s = 0.f;
#pragma unroll
    for (int k = 0; k < NSPLIT; k++) s += part[(long long)k * stride + i];
    out[i] = s;
}

// ---------------- softmax over rows (warp per row), in place -------------
__global__ void softmax_rows(float* __restrict__ x, int rows, int cols)
{
    const int row = blockIdx.x * (blockDim.x / 32) + (threadIdx.x / 32);
    if (row >= rows) return;
    const int lane = threadIdx.x & 31;
    float* p = x + (long long)row * cols;

    float m = -3.0e38f;
    for (int c = lane; c < cols; c += 32) m = fmaxf(m, p[c]);
#pragma unroll
    for (int o = 16; o; o >>= 1) m = fmaxf(m, __shfl_xor_sync(0xffffffffu, m, o));

    float s = 0.f;
    for (int c = lane; c < cols; c += 32) {
        float e = __expf(p[c] - m);
        p[c] = e;
        s += e;
    }
#pragma unroll
    for (int o = 16; o; o >>= 1) s += __shfl_xor_sync(0xffffffffu, s, o);

    const float inv = 1.f / s;
    for (int c = lane; c < cols; c += 32) p[c] *= inv;
}

// ---------------- launch helper ------------------------------------------
template<int BM, int BN, int WM, int WN, bool BTRANS>
static void launch_gemm(dim3 grid,
                        const float* A, long long sA, int lda,
                        const float* B, long long sB, int ldb,
                        float* C, long long sC, int ldc,
                        int Kloop,
                        const float* bias, float scale,
                        const float* lens,
                        int nsplit, long long sSplit)
{
    constexpr int SMEM = SmemSizes<BM, BN, BTRANS>::BYTES;
    cudaFuncSetAttribute(gemm_tc<BM, BN, WM, WN, BTRANS>,
                         cudaFuncAttributeMaxDynamicSharedMemorySize, SMEM);
    gemm_tc<BM, BN, WM, WN, BTRANS><<<grid, 256, SMEM>>>(
        A, sA, lda, B, sB, ldb, C, sC, ldc, Kloop, bias, scale, lens, nsplit, sSplit);
}

// ---------------- launch -------------------------------------------------
extern "C" void kernel_launch(void* const* d_in, const int* in_sizes, int n_in,
                              void* d_out, int out_size)
{
    const float* hs    = (const float*)d_in[0];
    const float* proto = (const float*)d_in[1];
    const float* lens  = (const float*)d_in[2];
    // d_in[3] = mask (bool) — unused; reconstructed from lens
    const float* Q1w = (const float*)d_in[4];
    const float* Q1b = (const float*)d_in[5];
    const float* K1w = (const float*)d_in[6];
    const float* K1b = (const float*)d_in[7];
    const float* V1w = (const float*)d_in[8];
    const float* V1b = (const float*)d_in[9];
    const float* Qw  = (const float*)d_in[10];
    const float* Qb  = (const float*)d_in[11];
    const float* Kw  = (const float*)d_in[12];
    const float* Kb  = (const float*)d_in[13];
    const float* Vw  = (const float*)d_in[14];
    const float* Vb  = (const float*)d_in[15];
    float* out = (float*)d_out;

    float *k1, *v1, *q2, *q1, *pf, *pfp, *k2, *v2, *s1, *s2;
    cudaGetSymbolAddress((void**)&k1, g_k1);
    cudaGetSymbolAddress((void**)&v1, g_v1);
    cudaGetSymbolAddress((void**)&q2, g_q2);
    cudaGetSymbolAddress((void**)&q1, g_q1);
    cudaGetSymbolAddress((void**)&pf, g_pf);
    cudaGetSymbolAddress((void**)&pfp, g_pfp);
    cudaGetSymbolAddress((void**)&k2, g_k2);
    cudaGetSymbolAddress((void**)&v2, g_v2);
    cudaGetSymbolAddress((void**)&s1, g_s1);
    cudaGetSymbolAddress((void**)&s2, g_s2);

    const int BT = BB * TT;        // 65536
    const int BP = BB * PP;        // 1024
    const long long TH = (long long)TT * HH;
    const long long PH = (long long)PP * HH;
    const long long PT = (long long)PP * TT;
    const long long TP = (long long)TT * PP;

    // q1 = proto @ Q1_w^T + Q1_b                    [64, 256]
    launch_gemm<64, 128, 32, 32, true>(dim3(HH / 128, 1, 1),
        proto, 0, HH, Q1w, 0, HH, q1, 0, HH, HH, Q1b, 1.f, nullptr, 1, 0);

    // k1 / v1 / q2 over all tokens                  [65536, 256]
    launch_gemm<128, 128, 64, 32, true>(dim3(HH / 128, BT / 128, 1),
        hs, 0, HH, K1w, 0, HH, k1, 0, HH, HH, K1b, 1.f, nullptr, 1, 0);
    launch_gemm<128, 128, 64, 32, true>(dim3(HH / 128, BT / 128, 1),
        hs, 0, HH, V1w, 0, HH, v1, 0, HH, HH, V1b, 1.f, nullptr, 1, 0);
    launch_gemm<128, 128, 64, 32, true>(dim3(HH / 128, BT / 128, 1),
        hs, 0, HH, Qw, 0, HH, q2, 0, HH, HH, Qb, 1.f, nullptr, 1, 0);

    // scores1[b,p,t] = q1 . k1 * rsqrt(len_b), masked (t >= len -> -1e9)
    launch_gemm<64, 128, 32, 32, true>(dim3(TT / 128, 1, BB),
        q1, 0, HH, k1, TH, HH, s1, PT, TT, HH, nullptr, 1.f, lens, 1, 0);

    softmax_rows<<<BP / 8, 256>>>(s1, BP, TT);

    // pf[b] = attn1 @ v1   (split-K x8)             [64, 256] per batch
    launch_gemm<64, 64, 32, 16, false>(dim3(HH / 64, 1, BB * NSPLIT),
        s1, PT, TT, v1, TH, HH, pfp, PH, HH, TT / NSPLIT,
        nullptr, 1.f, nullptr, NSPLIT, (long long)BB * PP * HH);
    reduce_splits<<<(BB * PP * HH + 255) / 256, 256>>>(
        pfp, pf, BB * PP * HH, (long long)BB * PP * HH);

    // k2 / v2 = pf @ {K,V}_w^T + b                  [1024, 256]
    launch_gemm<64, 128, 32, 32, true>(dim3(HH / 128, BP / 64, 1),
        pf, 0, HH, Kw, 0, HH, k2, 0, HH, HH, Kb, 1.f, nullptr, 1, 0);
    launch_gemm<64, 128, 32, 32, true>(dim3(HH / 128, BP / 64, 1),
        pf, 0, HH, Vw, 0, HH, v2, 0, HH, HH, Vb, 1.f, nullptr, 1, 0);

    // scores2[b,t,p] = q2 . k2 / sqrt(P)
    launch_gemm<128, 64, 32, 32, true>(dim3(PP / 64, TT / 128, BB),
        q2, TH, HH, k2, PH, HH, s2, TP, PP, HH, nullptr, 0.125f, nullptr, 1, 0);

    softmax_rows<<<BT / 8, 256>>>(s2, BT, PP);

    // out[b] = attn2 @ v2                           [4096, 256] per batch
    launch_gemm<128, 128, 64, 32, false>(dim3(HH / 128, TT / 128, BB),
        s2, TP, PP, v2, PH, HH, out, TH, HH, PP, nullptr, 1.f, nullptr, 1, 0);
}

// round 9
// speedup vs baseline: 5.9930x; 1.0499x over previous
#include <cuda_runtime.h>
#include <cuda_bf16.h>
#include <math.h>

// Problem dims (fixed by the dataset)
#define BB 16
#define TT 4096
#define HH 256
#define PP 64

#define NSPLIT 8   // split-K factor for the pf GEMM

// ---------------- scratch (no allocation allowed) ----------------
__device__ float g_k1[BB * TT * HH];   // 64 MB
__device__ float g_v1[BB * TT * HH];   // 64 MB
__device__ float g_q2[BB * TT * HH];   // 64 MB
__device__ float g_q1[PP * HH];
__device__ float g_pf[BB * PP * HH];
__device__ float g_pfp[NSPLIT * BB * PP * HH];  // split-K partials (8 MB)
__device__ float g_k2[BB * PP * HH];
__device__ float g_v2[BB * PP * HH];
__device__ float g_s1[BB * PP * TT];   // 16 MB
__device__ float g_s2[BB * TT * PP];   // 16 MB
__device__ float g_wr[6 * HH * HH];    // pre-rounded weights (1.5 MB)

// ---------------- helpers ------------------------------------------------
__device__ __forceinline__ void mma_tf32(float* c, const unsigned* a, const unsigned* b) {
    asm("mma.sync.aligned.m16n8k8.row.col.f32.tf32.tf32.f32 "
        "{%0,%1,%2,%3},{%4,%5,%6,%7},{%8,%9},{%0,%1,%2,%3};"
        : "+f"(c[0]), "+f"(c[1]), "+f"(c[2]), "+f"(c[3])
        : "r"(a[0]), "r"(a[1]), "r"(a[2]), "r"(a[3]), "r"(b[0]), "r"(b[1]));
}

// RNA round to the tf32 grid. MMA truncation of such a value is the identity,
// so pre-rounded producers give bit-identical results to consumer-side rnd13.
__device__ __forceinline__ unsigned rnd13(unsigned u) { return u + 0x1000u; }
__device__ __forceinline__ float roundtf(float f) {
    unsigned u = __float_as_uint(f);
    u = (u + 0x1000u) & 0xFFFFE000u;
    return __uint_as_float(u);
}

__device__ __forceinline__ void ldsm_x4(unsigned& r0, unsigned& r1,
                                        unsigned& r2, unsigned& r3, unsigned addr) {
    asm volatile("ldmatrix.sync.aligned.m8n8.x4.shared.b16 {%0,%1,%2,%3}, [%4];"
                 : "=r"(r0), "=r"(r1), "=r"(r2), "=r"(r3) : "r"(addr));
}

__device__ __forceinline__ void cpa16s(unsigned dst, const void* src) {
    asm volatile("cp.async.cg.shared.global [%0], [%1], 16;" :: "r"(dst), "l"(src));
}
__device__ __forceinline__ void cp_commit() {
    asm volatile("cp.async.commit_group;");
}
template<int N>
__device__ __forceinline__ void cp_wait() {
    asm volatile("cp.async.wait_group %0;" :: "n"(N));
}

// ---------------- TF32 tensor-core GEMM, 3-stage cp.async + ldmatrix -----
// C[m,n] = sum_k A[m,k] * B'[k,n]
//   BTRANS=true :  B' = B^T with B [N,K] row-major (x @ W^T pattern)
//   BTRANS=false:  B' = B     with B [K,N] row-major
// RNDA: apply rnd13 to A fragments (for raw-fp32 A inputs: hs, proto).
// RNDOUT: round epilogue output to tf32 grid (for tensors feeding later MMAs).
// B operands must be pre-rounded by their producers.
#define BK 32
#define NSTG 3

template<int BM, int BN, bool BTRANS>
struct SmemSizes {
    static constexpr int AWORDS = BM * BK;
    static constexpr int BSTNN  = BN + 8;
    static constexpr int BWORDS = BTRANS ? BN * BK : BK * BSTNN;
    static constexpr int STW    = AWORDS + BWORDS;     // words per stage
    static constexpr int BYTES  = NSTG * STW * 4;
};

template<int BM, int BN, int WM, int WN, bool BTRANS, bool RNDA, bool RNDOUT>
__global__ __launch_bounds__(256, 2) void gemm_tc(
    const float* __restrict__ A, long long sA, int lda,
    const float* __restrict__ B, long long sB, int ldb,
    float* __restrict__ C, long long sC, int ldc,
    int Kloop,
    const float* __restrict__ bias, float scale,
    const float* __restrict__ lens,
    int nsplit, long long sSplit)
{
    constexpr int WCOLS = BN / WN;
    constexpr int MT  = WM / 16;    // m16 tiles per warp
    constexpr int NTt = WN / 8;     // n8 tiles per warp
    constexpr int NJ  = NTt / 2;    // ldmatrix.x4 covers 2 n8 tiles
    constexpr int AWORDS = SmemSizes<BM, BN, BTRANS>::AWORDS;
    constexpr int BSTNN  = SmemSizes<BM, BN, BTRANS>::BSTNN;
    constexpr int STW    = SmemSizes<BM, BN, BTRANS>::STW;

    extern __shared__ unsigned smem_dyn[];
    const unsigned sbase = (unsigned)__cvta_generic_to_shared(smem_dyn);

    const int bz = blockIdx.z;
    const int b  = bz / nsplit;
    const int ks = bz % nsplit;

    const float* Ab = A + (long long)b * sA + (long long)ks * Kloop;
    const float* Bb;
    if (BTRANS) Bb = B + (long long)b * sB + (long long)ks * Kloop;
    else        Bb = B + (long long)b * sB + (long long)ks * Kloop * ldb;
    float* Cb = C + (long long)b * sC + (long long)ks * sSplit;

    const int m0 = blockIdx.y * BM;
    const int n0 = blockIdx.x * BN;

    float maskLen = 3.0e38f;
    if (lens) {
        float L = lens[b];
        scale = rsqrtf(L);
        maskLen = L;
    }

    const int tid  = threadIdx.x;
    const int lane = tid & 31;
    const int wid  = tid >> 5;
    const int wm   = wid / WCOLS;
    const int wn   = wid % WCOLS;
    const int g    = lane >> 2;     // groupID 0..7
    const int t4   = lane & 3;      // thread-in-group 0..3
    const int l7   = lane & 7;
    const int lr15 = lane & 15;
    const int hb   = lane >> 4;         // 0/1 : quad-select for A ldmatrix
    const int qb   = (lane >> 3) & 1;   // 0/1 : quad-select for B ldmatrix

    // loader indices for swizzled [row][k] tiles: 32 rows x 8 quads per pass
    const int ar = tid >> 3;        // 0..31
    const int aq = tid & 7;         // quad 0..7

    auto loadA = [&](int s, int k0) {
        const unsigned abase = sbase + (s * STW) * 4;
#pragma unroll
        for (int i = 0; i < BM / 32; i++) {
            const int row = ar + 32 * i;
            cpa16s(abase + (row * BK + ((aq ^ (row & 7)) << 2)) * 4,
                   Ab + (long long)(m0 + row) * lda + k0 + (aq << 2));
        }
    };
    auto loadB = [&](int s, int k0) {
        const unsigned bbase = sbase + (s * STW + AWORDS) * 4;
        if (BTRANS) {
#pragma unroll
            for (int i = 0; i < BN / 32; i++) {
                const int row = ar + 32 * i;
                cpa16s(bbase + (row * BK + ((aq ^ (row & 7)) << 2)) * 4,
                       Bb + (long long)(n0 + row) * ldb + k0 + (aq << 2));
            }
        } else {
            constexpr int QPR = BN / 4;          // quads per k-row
            constexpr int RPP = 256 / QPR;       // k-rows per pass
            const int bk = tid / QPR;
            const int bq = tid % QPR;
#pragma unroll
            for (int i = 0; i < BK / RPP; i++) {
                const int krow = bk + RPP * i;
                cpa16s(bbase + (krow * BSTNN + bq * 4) * 4,
                       Bb + (long long)(k0 + krow) * ldb + n0 + bq * 4);
            }
        }
    };

    // per-lane ldmatrix row offsets (stage-independent, bytes)
    unsigned aRowOff[MT];
#pragma unroll
    for (int i = 0; i < MT; i++)
        aRowOff[i] = (wm * WM + i * 16 + lr15) * BK * 4;
    unsigned bRowOff[NJ];
    if (BTRANS) {
#pragma unroll
        for (int jj = 0; jj < NJ; jj++)
            bRowOff[jj] = (wn * WN + jj * 16 + hb * 8 + l7) * BK * 4;
    }

    float acc[MT][NTt][4];
#pragma unroll
    for (int i = 0; i < MT; i++)
#pragma unroll
        for (int j = 0; j < NTt; j++)
#pragma unroll
            for (int q = 0; q < 4; q++) acc[i][j][q] = 0.f;

    const int nIter = Kloop / BK;

    // prologue: prefetch stages 0,1 (always 2 committed groups)
    loadA(0, 0);
    loadB(0, 0);
    cp_commit();
    if (nIter > 1) { loadA(1, BK); loadB(1, BK); }
    cp_commit();

    int cb = 0;
    for (int it = 0; it < nIter; it++) {
        if (it + 2 < nIter) {
            const int nbuf = (cb == 0) ? 2 : cb - 1;   // (cb+2) mod 3
            loadA(nbuf, (it + 2) * BK);
            loadB(nbuf, (it + 2) * BK);
        }
        cp_commit();          // may be an empty group (keeps FIFO uniform)
        cp_wait<2>();
        __syncthreads();

        const unsigned aSt = sbase + (cb * STW) * 4;
        const unsigned bSt = aSt + AWORDS * 4;
        const unsigned* BsNN = smem_dyn + cb * STW + AWORDS;

#pragma unroll
        for (int kss = 0; kss < BK / 8; kss++) {
            const int q0 = kss * 2;
            unsigned af[MT][4];
#pragma unroll
            for (int i = 0; i < MT; i++) {
                ldsm_x4(af[i][0], af[i][1], af[i][2], af[i][3],
                        aSt + aRowOff[i] + (unsigned)((((q0 + hb) ^ l7)) << 4));
                if (RNDA) {
                    af[i][0] = rnd13(af[i][0]); af[i][1] = rnd13(af[i][1]);
                    af[i][2] = rnd13(af[i][2]); af[i][3] = rnd13(af[i][3]);
                }
            }
            unsigned bf[NTt][2];
            if (BTRANS) {
#pragma unroll
                for (int jj = 0; jj < NJ; jj++) {
                    unsigned w0, w1, w2, w3;
                    ldsm_x4(w0, w1, w2, w3,
                            bSt + bRowOff[jj] + (unsigned)((((q0 + qb) ^ l7)) << 4));
                    bf[2 * jj][0]     = w0;
                    bf[2 * jj][1]     = w1;
                    bf[2 * jj + 1][0] = w2;
                    bf[2 * jj + 1][1] = w3;
                }
            } else {
                const int kb = kss * 8;
#pragma unroll
                for (int j = 0; j < NTt; j++) {
                    const int n = wn * WN + j * 8 + g;
                    bf[j][0] = BsNN[(kb + t4)     * BSTNN + n];
                    bf[j][1] = BsNN[(kb + t4 + 4) * BSTNN + n];
                }
            }
#pragma unroll
            for (int i = 0; i < MT; i++)
#pragma unroll
                for (int j = 0; j < NTt; j++)
                    mma_tf32(acc[i][j], af[i], bf[j]);
        }
        __syncthreads();
        cb = (cb == 2) ? 0 : cb + 1;
    }

    // ---- epilogue ----
#pragma unroll
    for (int i = 0; i < MT; i++) {
        const int mrow = m0 + wm * WM + i * 16 + g;
#pragma unroll
        for (int j = 0; j < NTt; j++) {
            const int ncol = n0 + wn * WN + j * 8 + 2 * t4;
            float b0 = bias ? bias[ncol]     : 0.f;
            float b1 = bias ? bias[ncol + 1] : 0.f;
            float v0 = acc[i][j][0] * scale + b0;
            float v1 = acc[i][j][1] * scale + b1;
            float v2 = acc[i][j][2] * scale + b0;
            float v3 = acc[i][j][3] * scale + b1;
            if (lens) {
                if ((float)ncol     >= maskLen) { v0 = -1e9f; v2 = -1e9f; }
                if ((float)(ncol+1) >= maskLen) { v1 = -1e9f; v3 = -1e9f; }
            }
            if (RNDOUT) {
                v0 = roundtf(v0); v1 = roundtf(v1);
                v2 = roundtf(v2); v3 = roundtf(v3);
            }
            *(float2*)(Cb + (long long)mrow * ldc + ncol)       = make_float2(v0, v1);
            *(float2*)(Cb + (long long)(mrow + 8) * ldc + ncol) = make_float2(v2, v3);
        }
    }
}

// ---------------- weight pre-round (6 matrices in one launch) ------------
__global__ void round6(const float* w0, const float* w1, const float* w2,
                       const float* w3, const float* w4, const float* w5,
                       float* dst)
{
    const int seg = blockIdx.y;
    const float* src;
    switch (seg) {
        case 0: src = w0; break; case 1: src = w1; break;
        case 2: src = w2; break; case 3: src = w3; break;
        case 4: src = w4; break; default: src = w5; break;
    }
    const int i = blockIdx.x * blockDim.x + threadIdx.x;
    dst[seg * HH * HH + i] = roundtf(src[i]);
}

// ---------------- split-K reduce (rounds: pf feeds later MMAs) -----------
__global__ void reduce_splits(const float* __restrict__ part,
                              float* __restrict__ out,
                              int n, long long stride)
{
    const int i = blockIdx.x * blockDim.x + threadIdx.x;
    if (i >= n) return;
    float s = 0.f;
#pragma unroll
    for (int k = 0; k < NSPLIT; k++) s += part[(long long)k * stride + i];
    out[i] = roundtf(s);
}

// ---------------- softmax over rows, in place; writes tf32-rounded -------
__global__ void softmax_rows(float* __restrict__ x, int rows, int cols)
{
    const int row = blockIdx.x * (blockDim.x / 32) + (threadIdx.x / 32);
    if (row >= rows) return;
    const int lane = threadIdx.x & 31;
    float* p = x + (long long)row * cols;

    float m = -3.0e38f;
    for (int c = lane; c < cols; c += 32) m = fmaxf(m, p[c]);
#pragma unroll
    for (int o = 16; o; o >>= 1) m = fmaxf(m, __shfl_xor_sync(0xffffffffu, m, o));

    float s = 0.f;
    for (int c = lane; c < cols; c += 32) {
        float e = __expf(p[c] - m);
        p[c] = e;
        s += e;
    }
#pragma unroll
    for (int o = 16; o; o >>= 1) s += __shfl_xor_sync(0xffffffffu, s, o);

    const float inv = 1.f / s;
    for (int c = lane; c < cols; c += 32) p[c] = roundtf(p[c] * inv);
}

// ---------------- launch helper ------------------------------------------
template<int BM, int BN, int WM, int WN, bool BTRANS, bool RNDA, bool RNDOUT>
static void launch_gemm(dim3 grid,
                        const float* A, long long sA, int lda,
                        const float* B, long long sB, int ldb,
                        float* C, long long sC, int ldc,
                        int Kloop,
                        const float* bias, float scale,
                        const float* lens,
                        int nsplit, long long sSplit)
{
    constexpr int SMEM = SmemSizes<BM, BN, BTRANS>::BYTES;
    cudaFuncSetAttribute(gemm_tc<BM, BN, WM, WN, BTRANS, RNDA, RNDOUT>,
                         cudaFuncAttributeMaxDynamicSharedMemorySize, SMEM);
    gemm_tc<BM, BN, WM, WN, BTRANS, RNDA, RNDOUT><<<grid, 256, SMEM>>>(
        A, sA, lda, B, sB, ldb, C, sC, ldc, Kloop, bias, scale, lens, nsplit, sSplit);
}

// ---------------- launch -------------------------------------------------
extern "C" void kernel_launch(void* const* d_in, const int* in_sizes, int n_in,
                              void* d_out, int out_size)
{
    const float* hs    = (const float*)d_in[0];
    const float* proto = (const float*)d_in[1];
    const float* lens  = (const float*)d_in[2];
    // d_in[3] = mask (bool) — unused; reconstructed from lens
    const float* Q1w = (const float*)d_in[4];
    const float* Q1b = (const float*)d_in[5];
    const float* K1w = (const float*)d_in[6];
    const float* K1b = (const float*)d_in[7];
    const float* V1w = (const float*)d_in[8];
    const float* V1b = (const float*)d_in[9];
    const float* Qw  = (const float*)d_in[10];
    const float* Qb  = (const float*)d_in[11];
    const float* Kw  = (const float*)d_in[12];
    const float* Kb  = (const float*)d_in[13];
    const float* Vw  = (const float*)d_in[14];
    const float* Vb  = (const float*)d_in[15];
    float* out = (float*)d_out;

    float *k1, *v1, *q2, *q1, *pf, *pfp, *k2, *v2, *s1, *s2, *wr;
    cudaGetSymbolAddress((void**)&k1, g_k1);
    cudaGetSymbolAddress((void**)&v1, g_v1);
    cudaGetSymbolAddress((void**)&q2, g_q2);
    cudaGetSymbolAddress((void**)&q1, g_q1);
    cudaGetSymbolAddress((void**)&pf, g_pf);
    cudaGetSymbolAddress((void**)&pfp, g_pfp);
    cudaGetSymbolAddress((void**)&k2, g_k2);
    cudaGetSymbolAddress((void**)&v2, g_v2);
    cudaGetSymbolAddress((void**)&s1, g_s1);
    cudaGetSymbolAddress((void**)&s2, g_s2);
    cudaGetSymbolAddress((void**)&wr, g_wr);

    const int BT = BB * TT;        // 65536
    const int BP = BB * PP;        // 1024
    const long long TH = (long long)TT * HH;
    const long long PH = (long long)PP * HH;
    const long long PT = (long long)PP * TT;
    const long long TP = (long long)TT * PP;

    // pre-round the 6 weight matrices to the tf32 grid
    round6<<<dim3(HH * HH / 1024, 6), 1024>>>(Q1w, K1w, V1w, Qw, Kw, Vw, wr);
    const float* rQ1w = wr + 0 * HH * HH;
    const float* rK1w = wr + 1 * HH * HH;
    const float* rV1w = wr + 2 * HH * HH;
    const float* rQw  = wr + 3 * HH * HH;
    const float* rKw  = wr + 4 * HH * HH;
    const float* rVw  = wr + 5 * HH * HH;

    // q1 = proto @ Q1_w^T + Q1_b                    [64, 256]
    launch_gemm<64, 128, 32, 32, true, true, true>(dim3(HH / 128, 1, 1),
        proto, 0, HH, rQ1w, 0, HH, q1, 0, HH, HH, Q1b, 1.f, nullptr, 1, 0);

    // k1 / v1 / q2 over all tokens                  [65536, 256]
    launch_gemm<128, 128, 64, 32, true, true, true>(dim3(HH / 128, BT / 128, 1),
        hs, 0, HH, rK1w, 0, HH, k1, 0, HH, HH, K1b, 1.f, nullptr, 1, 0);
    launch_gemm<128, 128, 64, 32, true, true, true>(dim3(HH / 128, BT / 128, 1),
        hs, 0, HH, rV1w, 0, HH, v1, 0, HH, HH, V1b, 1.f, nullptr, 1, 0);
    launch_gemm<128, 128, 64, 32, true, true, true>(dim3(HH / 128, BT / 128, 1),
        hs, 0, HH, rQw, 0, HH, q2, 0, HH, HH, Qb, 1.f, nullptr, 1, 0);

    // scores1[b,p,t] = q1 . k1 * rsqrt(len_b), masked (t >= len -> -1e9)
    launch_gemm<64, 128, 32, 32, true, false, false>(dim3(TT / 128, 1, BB),
        q1, 0, HH, k1, TH, HH, s1, PT, TT, HH, nullptr, 1.f, lens, 1, 0);

    softmax_rows<<<BP / 8, 256>>>(s1, BP, TT);

    // pf[b] = attn1 @ v1   (split-K x8)             [64, 256] per batch
    launch_gemm<64, 64, 32, 16, false, false, false>(dim3(HH / 64, 1, BB * NSPLIT),
        s1, PT, TT, v1, TH, HH, pfp, PH, HH, TT / NSPLIT,
        nullptr, 1.f, nullptr, NSPLIT, (long long)BB * PP * HH);
    reduce_splits<<<(BB * PP * HH + 255) / 256, 256>>>(
        pfp, pf, BB * PP * HH, (long long)BB * PP * HH);

    // k2 / v2 = pf @ {K,V}_w^T + b                  [1024, 256]
    launch_gemm<64, 128, 32, 32, true, false, true>(dim3(HH / 128, BP / 64, 1),
        pf, 0, HH, rKw, 0, HH, k2, 0, HH, HH, Kb, 1.f, nullptr, 1, 0);
    launch_gemm<64, 128, 32, 32, true, false, true>(dim3(HH / 128, BP / 64, 1),
        pf, 0, HH, rVw, 0, HH, v2, 0, HH, HH, Vb, 1.f, nullptr, 1, 0);

    // scores2[b,t,p] = q2 . k2 / sqrt(P)
    launch_gemm<128, 64, 32, 32, true, false, false>(dim3(PP / 64, TT / 128, BB),
        q2, TH, HH, k2, PH, HH, s2, TP, PP, HH, nullptr, 0.125f, nullptr, 1, 0);

    softmax_rows<<<BT / 8, 256>>>(s2, BT, PP);

    // out[b] = attn2 @ v2                           [4096, 256] per batch
    launch_gemm<128, 128, 64, 32, false, false, false>(dim3(HH / 128, TT / 128, BB),
        s2, TP, PP, v2, PH, HH, out, TH, HH, PP, nullptr, 1.f, nullptr, 1, 0);
}

// round 12
// speedup vs baseline: 6.0038x; 1.0018x over previous
#include <cuda_runtime.h>
#include <cuda_bf16.h>
#include <math.h>

// Problem dims (fixed by the dataset)
#define BB 16
#define TT 4096
#define HH 256
#define PP 64

#define NSPLIT 8   // split-K factor for the pf GEMM
#define NF 768     // fused k1|v1|q2 width

// ---------------- scratch (no allocation allowed) ----------------
__device__ float g_kvq[BB * TT * NF];  // fused [k1 | v1 | q2], 192 MB
__device__ float g_q1[PP * HH];
__device__ float g_pf[BB * PP * HH];
__device__ float g_pfp[NSPLIT * BB * PP * HH];  // split-K partials (8 MB)
__device__ float g_k2[BB * PP * HH];
__device__ float g_v2[BB * PP * HH];
__device__ float g_s1[BB * PP * TT];   // 16 MB; reused as s2 (stream-ordered:
                                       // s1 dead after pf split-K GEMM reads it)
__device__ float g_wf[NF * HH];        // fused rounded weights [K1w;V1w;Qw]
__device__ float g_wr2[3 * HH * HH];   // rounded Q1w, Kw, Vw
__device__ float g_b3[NF];             // fused biases [K1b;V1b;Qb]

// ---------------- helpers ------------------------------------------------
__device__ __forceinline__ void mma_tf32(float* c, const unsigned* a, const unsigned* b) {
    asm("mma.sync.aligned.m16n8k8.row.col.f32.tf32.tf32.f32 "
        "{%0,%1,%2,%3},{%4,%5,%6,%7},{%8,%9},{%0,%1,%2,%3};"
        : "+f"(c[0]), "+f"(c[1]), "+f"(c[2]), "+f"(c[3])
        : "r"(a[0]), "r"(a[1]), "r"(a[2]), "r"(a[3]), "r"(b[0]), "r"(b[1]));
}

// RNA round to the tf32 grid. MMA truncation of such a value is the identity,
// so pre-rounded producers give bit-identical results to consumer-side rnd13.
__device__ __forceinline__ unsigned rnd13(unsigned u) { return u + 0x1000u; }
__device__ __forceinline__ float roundtf(float f) {
    unsigned u = __float_as_uint(f);
    u = (u + 0x1000u) & 0xFFFFE000u;
    return __uint_as_float(u);
}

__device__ __forceinline__ void ldsm_x4(unsigned& r0, unsigned& r1,
                                        unsigned& r2, unsigned& r3, unsigned addr) {
    asm volatile("ldmatrix.sync.aligned.m8n8.x4.shared.b16 {%0,%1,%2,%3}, [%4];"
                 : "=r"(r0), "=r"(r1), "=r"(r2), "=r"(r3) : "r"(addr));
}

__device__ __forceinline__ void cpa16s(unsigned dst, const void* src) {
    asm volatile("cp.async.cg.shared.global [%0], [%1], 16;" :: "r"(dst), "l"(src));
}
__device__ __forceinline__ void cp_commit() {
    asm volatile("cp.async.commit_group;");
}
template<int N>
__device__ __forceinline__ void cp_wait() {
    asm volatile("cp.async.wait_group %0;" :: "n"(N));
}

// ---------------- TF32 tensor-core GEMM, 3-stage cp.async + ldmatrix -----
// C[m,n] = sum_k A[m,k] * B'[k,n]
//   BTRANS=true :  B' = B^T with B [N,K] row-major (x @ W^T pattern)
//   BTRANS=false:  B' = B     with B [K,N] row-major
// RNDA: rnd13 on A fragments (raw-fp32 A inputs: hs, proto).
// RNDOUT: round epilogue output to tf32 grid (tensors feeding later MMAs).
// lens: per-batch mask+scale (s1); CTAs fully beyond len exit early.
// klim: per-batch K limit (pf) — trailing K blocks are exact zeros, skipped.
#define BK 32
#define NSTG 3

template<int BM, int BN, bool BTRANS>
struct SmemSizes {
    static constexpr int AWORDS = BM * BK;
    static constexpr int BSTNN  = BN + 8;
    static constexpr int BWORDS = BTRANS ? BN * BK : BK * BSTNN;
    static constexpr int STW    = AWORDS + BWORDS;     // words per stage
    static constexpr int BYTES  = NSTG * STW * 4;
};

template<int BM, int BN, int WM, int WN, bool BTRANS, bool RNDA, bool RNDOUT>
__global__ __launch_bounds__(256, 2) void gemm_tc(
    const float* __restrict__ A, long long sA, int lda,
    const float* __restrict__ B, long long sB, int ldb,
    float* __restrict__ C, long long sC, int ldc,
    int Kloop,
    const float* __restrict__ bias, float scale,
    const float* __restrict__ lens,
    const float* __restrict__ klim,
    int nsplit, long long sSplit)
{
    constexpr int WCOLS = BN / WN;
    constexpr int MT  = WM / 16;    // m16 tiles per warp
    constexpr int NTt = WN / 8;     // n8 tiles per warp
    constexpr int NJ  = NTt / 2;    // ldmatrix.x4 covers 2 n8 tiles
    constexpr int AWORDS = SmemSizes<BM, BN, BTRANS>::AWORDS;
    constexpr int BSTNN  = SmemSizes<BM, BN, BTRANS>::BSTNN;
    constexpr int STW    = SmemSizes<BM, BN, BTRANS>::STW;

    extern __shared__ unsigned smem_dyn[];
    const unsigned sbase = (unsigned)__cvta_generic_to_shared(smem_dyn);

    const int bz = blockIdx.z;
    const int b  = bz / nsplit;
    const int ks = bz % nsplit;

    const float* Ab = A + (long long)b * sA + (long long)ks * Kloop;
    const float* Bb;
    if (BTRANS) Bb = B + (long long)b * sB + (long long)ks * Kloop;
    else        Bb = B + (long long)b * sB + (long long)ks * Kloop * ldb;
    float* Cb = C + (long long)b * sC + (long long)ks * sSplit;

    const int m0 = blockIdx.y * BM;
    const int n0 = blockIdx.x * BN;

    float maskLen = 3.0e38f;
    if (lens) {
        float L = lens[b];
        scale = rsqrtf(L);
        maskLen = L;
        if ((float)n0 >= maskLen) return;   // tile fully masked; softmax zero-fills
    }

    int nIter = Kloop / BK;
    if (klim) {
        int eff = (int)klim[b] - ks * Kloop;
        eff = eff < 0 ? 0 : (eff > Kloop ? Kloop : eff);
        nIter = (eff + BK - 1) / BK;
    }

    const int tid  = threadIdx.x;
    const int lane = tid & 31;
    const int wid  = tid >> 5;
    const int wm   = wid / WCOLS;
    const int wn   = wid % WCOLS;
    const int g    = lane >> 2;     // groupID 0..7
    const int t4   = lane & 3;      // thread-in-group 0..3
    const int l7   = lane & 7;
    const int lr15 = lane & 15;
    const int hb   = lane >> 4;         // 0/1 : quad-select for A ldmatrix
    const int qb   = (lane >> 3) & 1;   // 0/1 : quad-select for B ldmatrix

    // loader indices for swizzled [row][k] tiles: 32 rows x 8 quads per pass
    const int ar = tid >> 3;        // 0..31
    const int aq = tid & 7;         // quad 0..7

    auto loadA = [&](int s, int k0) {
        const unsigned abase = sbase + (s * STW) * 4;
#pragma unroll
        for (int i = 0; i < BM / 32; i++) {
            const int row = ar + 32 * i;
            cpa16s(abase + (row * BK + ((aq ^ (row & 7)) << 2)) * 4,
                   Ab + (long long)(m0 + row) * lda + k0 + (aq << 2));
        }
    };
    auto loadB = [&](int s, int k0) {
        const unsigned bbase = sbase + (s * STW + AWORDS) * 4;
        if (BTRANS) {
#pragma unroll
            for (int i = 0; i < BN / 32; i++) {
                const int row = ar + 32 * i;
                cpa16s(bbase + (row * BK + ((aq ^ (row & 7)) << 2)) * 4,
                       Bb + (long long)(n0 + row) * ldb + k0 + (aq << 2));
            }
        } else {
            constexpr int QPR = BN / 4;          // quads per k-row
            constexpr int RPP = 256 / QPR;       // k-rows per pass
            const int bk = tid / QPR;
            const int bq = tid % QPR;
#pragma unroll
            for (int i = 0; i < BK / RPP; i++) {
                const int krow = bk + RPP * i;
                cpa16s(bbase + (krow * BSTNN + bq * 4) * 4,
                       Bb + (long long)(k0 + krow) * ldb + n0 + bq * 4);
            }
        }
    };

    // per-lane ldmatrix row offsets (stage-independent, bytes)
    unsigned aRowOff[MT];
#pragma unroll
    for (int i = 0; i < MT; i++)
        aRowOff[i] = (wm * WM + i * 16 + lr15) * BK * 4;
    unsigned bRowOff[NJ];
    if (BTRANS) {
#pragma unroll
        for (int jj = 0; jj < NJ; jj++)
            bRowOff[jj] = (wn * WN + jj * 16 + hb * 8 + l7) * BK * 4;
    }

    float acc[MT][NTt][4];
#pragma unroll
    for (int i = 0; i < MT; i++)
#pragma unroll
        for (int j = 0; j < NTt; j++)
#pragma unroll
            for (int q = 0; q < 4; q++) acc[i][j][q] = 0.f;

    if (nIter > 0) {
        // prologue: prefetch stages 0,1 (always 2 committed groups)
        loadA(0, 0);
        loadB(0, 0);
        cp_commit();
        if (nIter > 1) { loadA(1, BK); loadB(1, BK); }
        cp_commit();

        int cb = 0;
        for (int it = 0; it < nIter; it++) {
            if (it + 2 < nIter) {
                const int nbuf = (cb == 0) ? 2 : cb - 1;   // (cb+2) mod 3
                loadA(nbuf, (it + 2) * BK);
                loadB(nbuf, (it + 2) * BK);
            }
            cp_commit();          // may be an empty group (keeps FIFO uniform)
            cp_wait<2>();
            __syncthreads();

            const unsigned aSt = sbase + (cb * STW) * 4;
            const unsigned bSt = aSt + AWORDS * 4;
            const unsigned* BsNN = smem_dyn + cb * STW + AWORDS;

#pragma unroll
            for (int kss = 0; kss < BK / 8; kss++) {
                const int q0 = kss * 2;
                unsigned af[MT][4];
#pragma unroll
                for (int i = 0; i < MT; i++) {
                    ldsm_x4(af[i][0], af[i][1], af[i][2], af[i][3],
                            aSt + aRowOff[i] + (unsigned)((((q0 + hb) ^ l7)) << 4));
                    if (RNDA) {
                        af[i][0] = rnd13(af[i][0]); af[i][1] = rnd13(af[i][1]);
                        af[i][2] = rnd13(af[i][2]); af[i][3] = rnd13(af[i][3]);
                    }
                }
                unsigned bf[NTt][2];
                if (BTRANS) {
#pragma unroll
                    for (int jj = 0; jj < NJ; jj++) {
                        unsigned w0, w1, w2, w3;
                        ldsm_x4(w0, w1, w2, w3,
                                bSt + bRowOff[jj] + (unsigned)((((q0 + qb) ^ l7)) << 4));
                        bf[2 * jj][0]     = w0;
                        bf[2 * jj][1]     = w1;
                        bf[2 * jj + 1][0] = w2;
                        bf[2 * jj + 1][1] = w3;
                    }
                } else {
                    const int kb = kss * 8;
#pragma unroll
                    for (int j = 0; j < NTt; j++) {
                        const int n = wn * WN + j * 8 + g;
                        bf[j][0] = BsNN[(kb + t4)     * BSTNN + n];
                        bf[j][1] = BsNN[(kb + t4 + 4) * BSTNN + n];
                    }
                }
#pragma unroll
                for (int i = 0; i < MT; i++)
#pragma unroll
                    for (int j = 0; j < NTt; j++)
                        mma_tf32(acc[i][j], af[i], bf[j]);
            }
            __syncthreads();
            cb = (cb == 2) ? 0 : cb + 1;
        }
    }

    // ---- epilogue ----
#pragma unroll
    for (int i = 0; i < MT; i++) {
        const int mrow = m0 + wm * WM + i * 16 + g;
#pragma unroll
        for (int j = 0; j < NTt; j++) {
            const int ncol = n0 + wn * WN + j * 8 + 2 * t4;
            float b0 = bias ? bias[ncol]     : 0.f;
            float b1 = bias ? bias[ncol + 1] : 0.f;
            float v0 = acc[i][j][0] * scale + b0;
            float v1 = acc[i][j][1] * scale + b1;
            float v2 = acc[i][j][2] * scale + b0;
            float v3 = acc[i][j][3] * scale + b1;
            if (lens) {
                if ((float)ncol     >= maskLen) { v0 = -1e9f; v2 = -1e9f; }
                if ((float)(ncol+1) >= maskLen) { v1 = -1e9f; v3 = -1e9f; }
            }
            if (RNDOUT) {
                v0 = roundtf(v0); v1 = roundtf(v1);
                v2 = roundtf(v2); v3 = roundtf(v3);
            }
            *(float2*)(Cb + (long long)mrow * ldc + ncol)       = make_float2(v0, v1);
            *(float2*)(Cb + (long long)(mrow + 8) * ldc + ncol) = make_float2(v2, v3);
        }
    }
}

// ---------------- weight prep: round 6 matrices, build fused buffer ------
__global__ void prep_weights(const float* K1w, const float* V1w, const float* Qw,
                             const float* Q1w, const float* Kw, const float* Vw,
                             float* wf, float* wr2)
{
    const int seg = blockIdx.y;
    const float* src;
    switch (seg) {
        case 0: src = K1w; break; case 1: src = V1w; break;
        case 2: src = Qw;  break; case 3: src = Q1w; break;
        case 4: src = Kw;  break; default: src = Vw; break;
    }
    const int i = blockIdx.x * blockDim.x + threadIdx.x;
    const float v = roundtf(src[i]);
    if (seg < 3) wf[seg * HH * HH + i] = v;
    else         wr2[(seg - 3) * HH * HH + i] = v;
}

__global__ void fuse_bias(const float* K1b, const float* V1b, const float* Qb,
                          float* b3)
{
    const int j = blockIdx.x * blockDim.x + threadIdx.x;
    b3[j] = (j < 256) ? K1b[j] : (j < 512) ? V1b[j - 256] : Qb[j - 512];
}

// ---------------- split-K reduce (rounds: pf feeds later MMAs) -----------
__global__ void reduce_splits(const float* __restrict__ part,
                              float* __restrict__ out,
                              int n, long long stride)
{
    const int i = blockIdx.x * blockDim.x + threadIdx.x;
    if (i >= n) return;
    float s = 0.f;
#pragma unroll
    for (int k = 0; k < NSPLIT; k++) s += part[(long long)k * stride + i];
    out[i] = roundtf(s);
}

// ---------------- softmax over rows, in place; writes tf32-rounded -------
// lens: only cols < len are live (rest written as exact 0, matching the
// underflow-to-zero the full computation produced).
__global__ void softmax_rows(float* __restrict__ x, int rows, int cols,
                             const float* __restrict__ lens, int rpb)
{
    const int row = blockIdx.x * (blockDim.x / 32) + (threadIdx.x / 32);
    if (row >= rows) return;
    const int lane = threadIdx.x & 31;
    float* p = x + (long long)row * cols;

    int L = cols;
    if (lens) L = (int)lens[row / rpb];

    float m = -3.0e38f;
    for (int c = lane; c < L; c += 32) m = fmaxf(m, p[c]);
#pragma unroll
    for (int o = 16; o; o >>= 1) m = fmaxf(m, __shfl_xor_sync(0xffffffffu, m, o));

    float s = 0.f;
    for (int c = lane; c < L; c += 32) {
        float e = __expf(p[c] - m);
        p[c] = e;
        s += e;
    }
#pragma unroll
    for (int o = 16; o; o >>= 1) s += __shfl_xor_sync(0xffffffffu, s, o);

    const float inv = 1.f / s;
    for (int c = lane; c < L; c += 32) p[c] = roundtf(p[c] * inv);
    for (int c = L + lane; c < cols; c += 32) p[c] = 0.f;
}

// ---------------- launch helper ------------------------------------------
template<int BM, int BN, int WM, int WN, bool BTRANS, bool RNDA, bool RNDOUT>
static void launch_gemm(dim3 grid,
                        const float* A, long long sA, int lda,
                        const float* B, long long sB, int ldb,
                        float* C, long long sC, int ldc,
                        int Kloop,
                        const float* bias, float scale,
                        const float* lens, const float* klim,
                        int nsplit, long long sSplit)
{
    constexpr int SMEM = SmemSizes<BM, BN, BTRANS>::BYTES;
    cudaFuncSetAttribute(gemm_tc<BM, BN, WM, WN, BTRANS, RNDA, RNDOUT>,
                         cudaFuncAttributeMaxDynamicSharedMemorySize, SMEM);
    gemm_tc<BM, BN, WM, WN, BTRANS, RNDA, RNDOUT><<<grid, 256, SMEM>>>(
        A, sA, lda, B, sB, ldb, C, sC, ldc, Kloop, bias, scale, lens, klim,
        nsplit, sSplit);
}

// ---------------- launch -------------------------------------------------
extern "C" void kernel_launch(void* const* d_in, const int* in_sizes, int n_in,
                              void* d_out, int out_size)
{
    const float* hs    = (const float*)d_in[0];
    const float* proto = (const float*)d_in[1];
    const float* lens  = (const float*)d_in[2];
    // d_in[3] = mask (bool) — unused; reconstructed from lens
    const float* Q1w = (const float*)d_in[4];
    const float* Q1b = (const float*)d_in[5];
    const float* K1w = (const float*)d_in[6];
    const float* K1b = (const float*)d_in[7];
    const float* V1w = (const float*)d_in[8];
    const float* V1b = (const float*)d_in[9];
    const float* Qw  = (const float*)d_in[10];
    const float* Qb  = (const float*)d_in[11];
    const float* Kw  = (const float*)d_in[12];
    const float* Kb  = (const float*)d_in[13];
    const float* Vw  = (const float*)d_in[14];
    const float* Vb  = (const float*)d_in[15];
    float* out = (float*)d_out;

    float *kvq, *q1, *pf, *pfp, *k2, *v2, *s1, *wf, *wr2, *b3;
    cudaGetSymbolAddress((void**)&kvq, g_kvq);
    cudaGetSymbolAddress((void**)&q1, g_q1);
    cudaGetSymbolAddress((void**)&pf, g_pf);
    cudaGetSymbolAddress((void**)&pfp, g_pfp);
    cudaGetSymbolAddress((void**)&k2, g_k2);
    cudaGetSymbolAddress((void**)&v2, g_v2);
    cudaGetSymbolAddress((void**)&s1, g_s1);
    cudaGetSymbolAddress((void**)&wf, g_wf);
    cudaGetSymbolAddress((void**)&wr2, g_wr2);
    cudaGetSymbolAddress((void**)&b3, g_b3);
    float* s2 = s1;   // safe reuse: s1 fully consumed (pf GEMM) before scores2
                      // writes s2; enforced by stream ordering.

    const int BT = BB * TT;        // 65536
    const int BP = BB * PP;        // 1024
    const long long TH = (long long)TT * HH;
    const long long PH = (long long)PP * HH;
    const long long PT = (long long)PP * TT;
    const long long TP = (long long)TT * PP;
    const long long TF = (long long)TT * NF;

    // weight prep: round to tf32 grid; build fused [K1w;V1w;Qw] and bias
    prep_weights<<<dim3(HH * HH / 256, 6), 256>>>(K1w, V1w, Qw, Q1w, Kw, Vw, wf, wr2);
    fuse_bias<<<3, 256>>>(K1b, V1b, Qb, b3);
    const float* rQ1w = wr2 + 0 * HH * HH;
    const float* rKw  = wr2 + 1 * HH * HH;
    const float* rVw  = wr2 + 2 * HH * HH;

    // q1 = proto @ Q1_w^T + Q1_b                    [64, 256]
    launch_gemm<64, 128, 32, 32, true, true, true>(dim3(HH / 128, 1, 1),
        proto, 0, HH, rQ1w, 0, HH, q1, 0, HH, HH, Q1b, 1.f, nullptr, nullptr, 1, 0);

    // fused k1|v1|q2 over all tokens                [65536, 768]
    launch_gemm<128, 128, 64, 32, true, true, true>(dim3(NF / 128, BT / 128, 1),
        hs, 0, HH, wf, 0, HH, kvq, 0, NF, HH, b3, 1.f, nullptr, nullptr, 1, 0);

    // scores1[b,p,t] = q1 . k1 * rsqrt(len_b); tiles beyond len skipped
    launch_gemm<64, 128, 32, 32, true, false, false>(dim3(TT / 128, 1, BB),
        q1, 0, HH, kvq + 0, TF, NF, s1, PT, TT, HH, nullptr, 1.f, lens, nullptr, 1, 0);

    softmax_rows<<<BP / 8, 256>>>(s1, BP, TT, lens, PP);

    // pf[b] = attn1 @ v1   (split-K x8, per-batch K limit) [64, 256]/batch
    launch_gemm<64, 64, 32, 16, false, false, false>(dim3(HH / 64, 1, BB * NSPLIT),
        s1, PT, TT, kvq + 256, TF, NF, pfp, PH, HH, TT / NSPLIT,
        nullptr, 1.f, nullptr, lens, NSPLIT, (long long)BB * PP * HH);
    reduce_splits<<<(BB * PP * HH + 255) / 256, 256>>>(
        pfp, pf, BB * PP * HH, (long long)BB * PP * HH);

    // k2 / v2 = pf @ {K,V}_w^T + b                  [1024, 256]
    launch_gemm<64, 128, 32, 32, true, false, true>(dim3(HH / 128, BP / 64, 1),
        pf, 0, HH, rKw, 0, HH, k2, 0, HH, HH, Kb, 1.f, nullptr, nullptr, 1, 0);
    launch_gemm<64, 128, 32, 32, true, false, true>(dim3(HH / 128, BP / 64, 1),
        pf, 0, HH, rVw, 0, HH, v2, 0, HH, HH, Vb, 1.f, nullptr, nullptr, 1, 0);

    // scores2[b,t,p] = q2 . k2 / sqrt(P)   (s2 aliases s1's buffer)
    launch_gemm<128, 64, 32, 32, true, false, false>(dim3(PP / 64, TT / 128, BB),
        kvq + 512, TF, NF, k2, PH, HH, s2, TP, PP, HH,
        nullptr, 0.125f, nullptr, nullptr, 1, 0);

    softmax_rows<<<BT / 8, 256>>>(s2, BT, PP, nullptr, 1);

    // out[b] = attn2 @ v2                           [4096, 256] per batch
    launch_gemm<128, 128, 64, 32, false, false, false>(dim3(HH / 128, TT / 128, BB),
        s2, TP, PP, v2, PH, HH, out, TH, HH, PP, nullptr, 1.f, nullptr, nullptr, 1, 0);
}